// round 15
// baseline (speedup 1.0000x reference)
#include <cuda_runtime.h>
#include <cuda_fp16.h>
#include <cstddef>
#include <cstdint>

// Problem constants
#define M_TOK   8192     // M*B token rows
#define D_MODEL 1024
#define FF_DIM  4096
#define NHEAD   16
#define DHEAD   64
#define SEQ     1024
#define BATCH   8

// tcgen05 is arch-SPECIFIC (sm_103a). nvcc also runs a generic compute_103 PTX
// pass where these instructions don't exist — compile a stub there.
#if defined(__CUDA_ARCH__) && (defined(__CUDA_ARCH_FEAT_SM103_ALL) || defined(__CUDA_ARCH_SPECIFIC__))
#define HAS_TCGEN05 1
#else
#define HAS_TCGEN05 0
#endif

// ---------------- tcgen05 / TMA helpers ----------------
static constexpr uint64_t SMEM_DESC_BASE_SW128 =
    (uint64_t(2)  << 61) | (uint64_t(1) << 46) | (uint64_t(64) << 32) | (uint64_t(1) << 16);
#define MAKE_SMEM_DESC(base_addr) \
    (SMEM_DESC_BASE_SW128 | ((uint64_t)((base_addr) >> 4) & 0x3FFF))

__device__ __forceinline__ uint32_t smem_to_u32(const void* p) {
    uint32_t a;
    asm("{ .reg .u64 t; cvta.to.shared.u64 t, %1; cvt.u32.u64 %0, t; }" : "=r"(a) : "l"(p));
    return a;
}

#if HAS_TCGEN05
#define TCGEN05_ALLOC(smem_res, nCols) \
    asm volatile("tcgen05.alloc.cta_group::1.sync.aligned.shared::cta.b32 [%0], %1;" \
                 :: "r"((uint32_t)(smem_res)), "r"((uint32_t)(nCols)) : "memory")
#define TCGEN05_DEALLOC(tmem, nCols) \
    asm volatile("tcgen05.dealloc.cta_group::1.sync.aligned.b32 %0, %1;" \
                 :: "r"(tmem), "r"((uint32_t)(nCols)))
#define TCGEN05_RELINQUISH() \
    asm volatile("tcgen05.relinquish_alloc_permit.cta_group::1.sync.aligned;")
#define TCGEN05_WAIT_LD() asm volatile("tcgen05.wait::ld.sync.aligned;" ::: "memory")
#define TC_FENCE_AFTER()  asm volatile("tcgen05.fence::after_thread_sync;" ::: "memory")
#define TC_COMMIT(mbar) \
    asm volatile("tcgen05.commit.cta_group::1.mbarrier::arrive::one.shared::cluster.b64 [%0];" \
                 :: "r"((uint32_t)(mbar)) : "memory")
#define TC_COMMIT_MC(mbar, mask) \
    asm volatile("tcgen05.commit.cta_group::1.mbarrier::arrive::one.shared::cluster.multicast::cluster.b64 [%0], %1;" \
                 :: "r"((uint32_t)(mbar)), "h"((uint16_t)(mask)) : "memory")
#endif

#define FENCE_PROXY_ASYNC() asm volatile("fence.proxy.async.shared::cta;" ::: "memory")
#define MBARRIER_INIT(mbar, cnt) \
    asm volatile("mbarrier.init.shared.b64 [%0], %1;" :: "r"((uint32_t)(mbar)), "r"((uint32_t)(cnt)) : "memory")
#define MBARRIER_EXPECT_TX(mbar, bytes) \
    asm volatile("mbarrier.arrive.expect_tx.shared.b64 _, [%0], %1;" \
                 :: "r"((uint32_t)(mbar)), "r"((uint32_t)(bytes)) : "memory")
#define MBAR_WAIT(mbar, ph) \
    asm volatile("{\n\t.reg .pred P;\n\tWL%=:\n\t" \
                 "mbarrier.try_wait.parity.acquire.cta.shared::cta.b64 P, [%0], %1, 0x989680;\n\t" \
                 "@!P bra WL%=;\n\t}" :: "r"((uint32_t)(mbar)), "r"((uint32_t)(ph)) : "memory")
#define BULK_G2S(dst, src, bytes, mbar) \
    asm volatile("cp.async.bulk.shared::cta.global.mbarrier::complete_tx::bytes [%0], [%1], %2, [%3];" \
                 :: "r"((uint32_t)(dst)), "l"(src), "r"((uint32_t)(bytes)), "r"((uint32_t)(mbar)) : "memory")
#define BULK_G2S_MC(dst, src, bytes, mbar, mask) \
    asm volatile("cp.async.bulk.shared::cluster.global.mbarrier::complete_tx::bytes.multicast::cluster [%0], [%1], %2, [%3], %4;" \
                 :: "r"((uint32_t)(dst)), "l"(src), "r"((uint32_t)(bytes)), "r"((uint32_t)(mbar)), "h"((uint16_t)(mask)) : "memory")
#define CLUSTER_SYNC() do { \
    asm volatile("barrier.cluster.arrive.aligned;" ::: "memory"); \
    asm volatile("barrier.cluster.wait.aligned;" ::: "memory"); \
} while (0)

#if HAS_TCGEN05
#define TCGEN05_LD_32X32B_X32(r, tmem_addr) \
    asm volatile( \
        "tcgen05.ld.sync.aligned.32x32b.x32.b32 " \
        "{%0, %1, %2, %3, %4, %5, %6, %7, " \
        " %8, %9, %10, %11, %12, %13, %14, %15, " \
        " %16, %17, %18, %19, %20, %21, %22, %23, " \
        " %24, %25, %26, %27, %28, %29, %30, %31}, [%32];" \
        : "=r"((r)[0]),  "=r"((r)[1]),  "=r"((r)[2]),  "=r"((r)[3]), \
          "=r"((r)[4]),  "=r"((r)[5]),  "=r"((r)[6]),  "=r"((r)[7]), \
          "=r"((r)[8]),  "=r"((r)[9]),  "=r"((r)[10]), "=r"((r)[11]), \
          "=r"((r)[12]), "=r"((r)[13]), "=r"((r)[14]), "=r"((r)[15]), \
          "=r"((r)[16]), "=r"((r)[17]), "=r"((r)[18]), "=r"((r)[19]), \
          "=r"((r)[20]), "=r"((r)[21]), "=r"((r)[22]), "=r"((r)[23]), \
          "=r"((r)[24]), "=r"((r)[25]), "=r"((r)[26]), "=r"((r)[27]), \
          "=r"((r)[28]), "=r"((r)[29]), "=r"((r)[30]), "=r"((r)[31]) \
        : "r"(tmem_addr))

// f16 SS MMA, cg1. idesc: dtype F32(1<<4) | atype F16(0) | btype F16(0)
//                        | (N/8)<<17 | (M/16)<<24
__device__ __forceinline__ void mma_f16_ss(uint32_t d_tmem, uint64_t a_desc, uint64_t b_desc,
                                           uint32_t idesc, uint32_t en)
{
    asm volatile(
        "{\n\t"
        ".reg .pred p;\n\t"
        "setp.ne.u32 p, %5, 0;\n\t"
        "tcgen05.mma.cta_group::1.kind::f16 [%0], %1, %2, %3, {%4, %4, %4, %4}, p;\n\t"
        "}"
        :: "r"(d_tmem), "l"(a_desc), "l"(b_desc), "r"(idesc), "r"(0u), "r"(en)
        : "memory");
}
#endif

// ============ chunked + pre-swizzled fp16 GEMM operand layout =================
__device__ __forceinline__ size_t hchunk_idx(int row, int k, int R) {
    return ((size_t)(k >> 6) * R + row) * 64 + ((((k >> 3) & 7) ^ (row & 7)) << 3) + (k & 7);
}

// ---------------- scratch (static device memory; float-array backing) --------
static const size_t OFF_XN    = 0;          // half [16][8192][64]
static const size_t OFF_V     = 4194304;    // half row-major [8192][1024]
static const size_t OFF_POOL  = 8388608;    // half chunked
static const size_t OFF_X2    = 12582912;   // fp32 [8192][1024]
static const size_t OFF_H     = 20971520;   // half chunked [64][8192][64]
static const size_t OFF_QS    = 37748736;
static const size_t OFF_KS    = 37879808;
static const size_t OFF_WQK   = 38010880;   // fp32 [1024][32]
static const size_t OFF_BQK   = 38043648;
static const size_t OFF_WVT   = 38043680;   // half chunked
static const size_t OFF_WOT   = 38567968;
static const size_t OFF_W1T   = 39092256;
static const size_t OFF_W2T   = 41189408;
static const size_t OFF_KSTAT = 43286560;
static const size_t SCRATCH_FLOATS = 43287072;

__device__ float g_scratch[SCRATCH_FLOATS];

// ---------------- LayerNorm: row-major fp32 in -> chunked fp16 out ----------
__global__ void __launch_bounds__(256)
ln_kernel(const float* __restrict__ x, const float* __restrict__ g,
          const float* __restrict__ bta, __half* __restrict__ y)
{
    const int row = blockIdx.x;
    const int tx  = threadIdx.x;
    const float4 v = ((const float4*)(x + (size_t)row * D_MODEL))[tx];

    float s  = v.x + v.y + v.z + v.w;
    float sq = v.x * v.x + v.y * v.y + v.z * v.z + v.w * v.w;
    #pragma unroll
    for (int o = 16; o; o >>= 1) {
        s  += __shfl_xor_sync(0xffffffffu, s,  o);
        sq += __shfl_xor_sync(0xffffffffu, sq, o);
    }
    __shared__ float ss[8], ssq[8];
    const int w = tx >> 5, l = tx & 31;
    if (l == 0) { ss[w] = s; ssq[w] = sq; }
    __syncthreads();
    s = 0.f; sq = 0.f;
    #pragma unroll
    for (int i = 0; i < 8; i++) { s += ss[i]; sq += ssq[i]; }

    const float mean = s * (1.f / D_MODEL);
    const float var  = sq * (1.f / D_MODEL) - mean * mean;
    const float rstd = rsqrtf(var + 1e-5f);

    const float4 gv = ((const float4*)g)[tx];
    const float4 bv = ((const float4*)bta)[tx];
    const __half2 h01 = __floats2half2_rn((v.x - mean) * rstd * gv.x + bv.x,
                                          (v.y - mean) * rstd * gv.y + bv.y);
    const __half2 h23 = __floats2half2_rn((v.z - mean) * rstd * gv.z + bv.z,
                                          (v.w - mean) * rstd * gv.w + bv.w);
    const size_t oidx = ((size_t)(tx >> 4) * M_TOK + row) * 64 +
                        ((((tx >> 1) & 7) ^ (row & 7)) << 3) + ((tx & 1) << 2);
    __half2* dst = (__half2*)(y + oidx);
    dst[0] = h01; dst[1] = h23;
}

// ---------------- merged transpose: all 4 weights -> chunked fp16 -----------
__global__ void __launch_bounds__(256)
transpose_all(const float* __restrict__ wv, const float* __restrict__ wo,
              const float* __restrict__ w1, const float* __restrict__ w2,
              __half* __restrict__ wvt, __half* __restrict__ wot,
              __half* __restrict__ w1t, __half* __restrict__ w2t)
{
    int bid = blockIdx.x;
    const float* in; __half* out; int N;
    if (bid < 1024)      { in = wv; out = wvt; N = 1024; }
    else if (bid < 2048) { bid -= 1024; in = wo; out = wot; N = 1024; }
    else if (bid < 6144) { bid -= 2048; in = w1; out = w1t; N = 4096; }
    else                 { bid -= 6144; in = w2; out = w2t; N = 1024; }
    const int nbx = N >> 5;
    const int n0 = (bid % nbx) << 5;
    const int k0 = (bid / nbx) << 5;

    __shared__ float t[32][33];
    const int tx = threadIdx.x & 31;
    const int ty = threadIdx.x >> 5;   // 0..7
    #pragma unroll
    for (int i = 0; i < 4; i++)
        t[ty + (i << 3)][tx] = in[(size_t)(k0 + ty + (i << 3)) * N + n0 + tx];
    __syncthreads();
    #pragma unroll
    for (int i = 0; i < 4; i++) {
        const int n = n0 + ty + (i << 3);
        const int k = k0 + tx;
        out[hchunk_idx(n, k, N)] = __float2half_rn(t[tx][ty + (i << 3)]);
    }
}

// ---------------- head-sum of wq/wk columns into combined [1024][32] ---------
__global__ void headsum_kernel(const float* __restrict__ wq, const float* __restrict__ bq,
                               const float* __restrict__ wk, const float* __restrict__ bk,
                               float* __restrict__ wqk, float* __restrict__ bqk)
{
    const int idx = blockIdx.x * blockDim.x + threadIdx.x;
    if (idx < D_MODEL * NHEAD) {
        const int d = idx >> 4, h = idx & 15;
        const float* pq = wq + (size_t)d * D_MODEL + h * DHEAD;
        const float* pk = wk + (size_t)d * D_MODEL + h * DHEAD;
        float sq = 0.f, sk = 0.f;
        #pragma unroll 8
        for (int i = 0; i < DHEAD; i++) { sq += pq[i]; sk += pk[i]; }
        wqk[d * 32 + h]      = sq;
        wqk[d * 32 + 16 + h] = sk;
    }
    if (idx < NHEAD) {
        float sq = 0.f, sk = 0.f;
        for (int i = 0; i < DHEAD; i++) {
            sq += bq[idx * DHEAD + i];
            sk += bk[idx * DHEAD + i];
        }
        bqk[idx] = sq; bqk[16 + idx] = sk;
    }
}

// ---------------- skinny GEMM v3: 256 blocks x 32 rows -----------------------
__global__ void __launch_bounds__(256)
qsks_gemm(const __half* __restrict__ xn, const float* __restrict__ wqk,
          const float* __restrict__ bqk, float* __restrict__ qs, float* __restrict__ ks)
{
    __shared__ __half Araw[2048];     // 32 rows x 64 halves = 256 uint4
    __shared__ float Wsm[64][36];

    const int tx = threadIdx.x;
    const int r  = tx >> 3;           // 0..31
    const int cg = tx & 7;
    const int brow = blockIdx.x << 5;
    const int p7 = r & 7;

    float acc[4];
    #pragma unroll
    for (int j = 0; j < 4; j++) acc[j] = 0.f;

    for (int chk = 0; chk < 16; chk++) {
        {
            const uint4* src = (const uint4*)(xn + ((size_t)chk * M_TOK + brow) * 64);
            ((uint4*)Araw)[tx] = src[tx];
        }
        {
            const int row = tx >> 3, c4 = (tx & 7) << 2;
            *(float4*)&Wsm[row][c4]      = *(const float4*)(wqk + (size_t)(chk * 64 + row) * 32 + c4);
            *(float4*)&Wsm[row + 32][c4] = *(const float4*)(wqk + (size_t)(chk * 64 + row + 32) * 32 + c4);
        }
        __syncthreads();

        #pragma unroll
        for (int j = 0; j < 8; j++) {
            const uint4 ab = *(const uint4*)&Araw[r * 64 + ((j ^ p7) << 3)];
            const __half2* hp = (const __half2*)&ab;
            #pragma unroll
            for (int e = 0; e < 4; e++) {
                const float2 f2 = __half22float2(hp[e]);
                const int kk = j * 8 + e * 2;
                {
                    const float4 w0 = *(const float4*)&Wsm[kk][cg * 4];
                    acc[0] = fmaf(f2.x, w0.x, acc[0]); acc[1] = fmaf(f2.x, w0.y, acc[1]);
                    acc[2] = fmaf(f2.x, w0.z, acc[2]); acc[3] = fmaf(f2.x, w0.w, acc[3]);
                }
                {
                    const float4 w0 = *(const float4*)&Wsm[kk + 1][cg * 4];
                    acc[0] = fmaf(f2.y, w0.x, acc[0]); acc[1] = fmaf(f2.y, w0.y, acc[1]);
                    acc[2] = fmaf(f2.y, w0.z, acc[2]); acc[3] = fmaf(f2.y, w0.w, acc[3]);
                }
            }
        }
        __syncthreads();
    }

    const size_t row = (size_t)(brow + r);
    #pragma unroll
    for (int j = 0; j < 4; j++) {
        const int c = cg * 4 + j;
        const float v = acc[j] + bqk[c];
        if (c < 16) qs[row * NHEAD + c]        = v;
        else        ks[row * NHEAD + (c - 16)] = v;
    }
}

// ---------------- per-(b,h) key stats ----------------------------------------
__global__ void __launch_bounds__(256)
kminmax_kernel(const float* __restrict__ ks, const unsigned char* __restrict__ mask,
               float4* __restrict__ kstat)
{
    const int bh = blockIdx.x;
    const int b  = bh >> 4;
    const int h  = bh & 15;
    const int tx = threadIdx.x;

    float kmx = -1e30f, kmn = 1e30f;
    int cnt = 0, anym = 0;
    for (int n = tx; n < SEQ; n += 256) {
        const float kv = ks[((size_t)n * BATCH + b) * NHEAD + h];
        if (mask[(size_t)n * BATCH + b]) anym = 1;
        else { kmx = fmaxf(kmx, kv); kmn = fminf(kmn, kv); cnt++; }
    }
    __shared__ float smx[256], smn[256];
    __shared__ int scnt[256], sany[256];
    smx[tx] = kmx; smn[tx] = kmn; scnt[tx] = cnt; sany[tx] = anym;
    __syncthreads();
    for (int o = 128; o; o >>= 1) {
        if (tx < o) {
            smx[tx] = fmaxf(smx[tx], smx[tx + o]);
            smn[tx] = fminf(smn[tx], smn[tx + o]);
            scnt[tx] += scnt[tx + o];
            sany[tx] |= sany[tx + o];
        }
        __syncthreads();
    }
    if (tx == 0)
        kstat[bh] = make_float4(smx[0], smn[0], sany[0] ? 1.f : 0.f, (float)scnt[0]);
}

// ======== tcgen05 f16 GEMM: 256x256 supertile, 2x2 cluster TMA multicast ========
// Cluster (2,2): CTAs with same blockIdx.y pair share A (cx==0 loads, multicast);
// CTAs with same blockIdx.x pair share B (cy==0 loads, multicast).
// done[s] is a cluster barrier (count 4): every consumer commits multicast 0xF.
#define TC_STAGES   3
#define TC_HDR      1024
#define TC_STAGE_SZ 65536
#define TC_SMEM_TOTAL (TC_HDR + TC_STAGES * TC_STAGE_SZ)   // 197632
#define TC_IDESC  ((1u << 4) | (32u << 17) | (8u << 24))   // f16, N=256, M=128

template<bool RELU, bool RESID, int OUTMODE>
__global__ void __launch_bounds__(256) __cluster_dims__(2, 2, 1)
sgemm_tc(const __half* __restrict__ A, const __half* __restrict__ Wt,
         const float* __restrict__ bias, const float* __restrict__ resid,
         void* __restrict__ C, int N, int K)
{
#if HAS_TCGEN05
    extern __shared__ char sm[];
    const uint32_t sb = smem_to_u32(sm);
    const int tx = threadIdx.x;
    const int brow = blockIdx.y << 8;
    const int bcol = blockIdx.x << 8;
    const int cx = blockIdx.x & 1;
    const int cy = blockIdx.y & 1;

    if ((tx >> 5) == 0) TCGEN05_ALLOC(sb, 512);
    if (tx == 0) {
        #pragma unroll
        for (int s = 0; s < TC_STAGES; s++) {
            MBARRIER_INIT(sb + 8 + s * 8, 1);    // full[s]: local expect_tx + tx
            MBARRIER_INIT(sb + 32 + s * 8, 4);   // done[s]: commits from all 4 CTAs
        }
    }
    __syncthreads();
    if ((tx >> 5) == 0) TCGEN05_RELINQUISH();
    uint32_t tmem;
    asm volatile("ld.shared.b32 %0, [%1];" : "=r"(tmem) : "r"(sb));

    CLUSTER_SYNC();   // all mbarriers initialized before any multicast targets them

    const int nchunk = K >> 6;

    if (tx == 0) {
        // ---- consumer: MMA issuer ----
        TC_FENCE_AFTER();
        int phF0 = 0, phF1 = 0, phF2 = 0;
        for (int i = 0; i < nchunk; i++) {
            const int s = i % TC_STAGES;
            int ph;
            if (s == 0)      { ph = phF0; phF0 ^= 1; }
            else if (s == 1) { ph = phF1; phF1 ^= 1; }
            else             { ph = phF2; phF2 ^= 1; }
            MBAR_WAIT(sb + 8 + s * 8, ph);
            const uint32_t abase = sb + TC_HDR + s * TC_STAGE_SZ;
            const uint64_t ad0 = MAKE_SMEM_DESC(abase);
            const uint64_t ad1 = MAKE_SMEM_DESC(abase + 16384);
            const uint64_t bd  = MAKE_SMEM_DESC(abase + 32768);
            #pragma unroll
            for (int k8 = 0; k8 < 4; k8++) {
                const uint32_t en = (i | k8) ? 1u : 0u;
                mma_f16_ss(tmem,       ad0 + 2 * k8, bd + 2 * k8, TC_IDESC, en);
                mma_f16_ss(tmem + 256, ad1 + 2 * k8, bd + 2 * k8, TC_IDESC, en);
            }
            TC_COMMIT_MC(sb + 32 + s * 8, 0xF);   // done[s] on all 4 cluster CTAs
        }
    } else if (tx == 32) {
        // ---- producer: every CTA expects tx; loaders multicast fills ----
        const bool loadA = (cx == 0);
        const bool loadB = (cy == 0);
        const uint16_t amask = (uint16_t)(0x3u << (2 * cy));       // row pair
        const uint16_t bmask = (uint16_t)(0x5u << cx);             // col pair
        #pragma unroll
        for (int i = 0; i < TC_STAGES; i++) {
            const uint32_t full = sb + 8 + i * 8;
            const uint32_t abase = sb + TC_HDR + i * TC_STAGE_SZ;
            MBARRIER_EXPECT_TX(full, 2 * 32768);
            if (loadA)
                BULK_G2S_MC(abase, A + ((size_t)i * M_TOK + brow) * 64, 32768, full, amask);
            if (loadB)
                BULK_G2S_MC(abase + 32768, Wt + ((size_t)i * N + bcol) * 64, 32768, full, bmask);
        }
        int phD0 = 0, phD1 = 0, phD2 = 0;
        for (int j = TC_STAGES; j < nchunk; j++) {
            const int s = j % TC_STAGES;
            int ph;
            if (s == 0)      { ph = phD0; phD0 ^= 1; }
            else if (s == 1) { ph = phD1; phD1 ^= 1; }
            else             { ph = phD2; phD2 ^= 1; }
            MBAR_WAIT(sb + 32 + s * 8, ph);   // all 4 CTAs finished chunk j-3
            const uint32_t abase = sb + TC_HDR + s * TC_STAGE_SZ;
            const uint32_t full = sb + 8 + s * 8;
            MBARRIER_EXPECT_TX(full, 2 * 32768);
            if (loadA)
                BULK_G2S_MC(abase, A + ((size_t)j * M_TOK + brow) * 64, 32768, full, amask);
            if (loadB)
                BULK_G2S_MC(abase + 32768, Wt + ((size_t)j * N + bcol) * 64, 32768, full, bmask);
        }
        // drain remaining dones
        for (int i = nchunk - TC_STAGES; i < nchunk; i++) {
            const int s = i % TC_STAGES;
            int ph;
            if (s == 0)      { ph = phD0; phD0 ^= 1; }
            else if (s == 1) { ph = phD1; phD1 ^= 1; }
            else             { ph = phD2; phD2 ^= 1; }
            MBAR_WAIT(sb + 32 + s * 8, ph);
        }
    }
    __syncthreads();
    TC_FENCE_AFTER();

    {
        const int w     = tx >> 5;
        const int lane  = tx & 31;
        const int mtile = w >> 2;
        const int row   = brow + (mtile << 7) + ((w & 3) << 5) + lane;
        const int rw7   = row & 7;
        #pragma unroll
        for (int slab = 0; slab < 4; slab++) {
            uint32_t d[64];
            TCGEN05_LD_32X32B_X32(d,      tmem + mtile * 256 + slab * 64);
            TCGEN05_LD_32X32B_X32(d + 32, tmem + mtile * 256 + slab * 64 + 32);
            TCGEN05_WAIT_LD();
            const int cb = bcol + slab * 64;
            const float* bp = bias + cb;
            const float* rp = RESID ? (resid + (size_t)row * N + cb) : nullptr;
            #pragma unroll
            for (int j = 0; j < 64; j += 4) {
                const float4 bv = *(const float4*)(bp + j);
                float4 o;
                o.x = __uint_as_float(d[j + 0]) + bv.x;
                o.y = __uint_as_float(d[j + 1]) + bv.y;
                o.z = __uint_as_float(d[j + 2]) + bv.z;
                o.w = __uint_as_float(d[j + 3]) + bv.w;
                if (RESID) {
                    const float4 rv = *(const float4*)(rp + j);
                    o.x += rv.x; o.y += rv.y; o.z += rv.z; o.w += rv.w;
                }
                if (RELU) {
                    o.x = fmaxf(o.x, 0.f); o.y = fmaxf(o.y, 0.f);
                    o.z = fmaxf(o.z, 0.f); o.w = fmaxf(o.w, 0.f);
                }
                if (OUTMODE == 1) {
                    const int col = cb + j;
                    const __half2 h01 = __floats2half2_rn(o.x, o.y);
                    const __half2 h23 = __floats2half2_rn(o.z, o.w);
                    const size_t oidx = ((size_t)(col >> 6) * M_TOK + row) * 64 +
                                        ((((col >> 3) & 7) ^ rw7) << 3) + (col & 7);
                    __half2* dst = (__half2*)((__half*)C + oidx);
                    dst[0] = h01; dst[1] = h23;
                } else if (OUTMODE == 2) {
                    const __half2 h01 = __floats2half2_rn(o.x, o.y);
                    const __half2 h23 = __floats2half2_rn(o.z, o.w);
                    __half2* dst = (__half2*)((__half*)C + (size_t)row * N + cb + j);
                    dst[0] = h01; dst[1] = h23;
                } else {
                    *(float4*)((float*)C + (size_t)row * N + cb + j) = o;
                }
            }
        }
    }

    __syncthreads();
    if ((tx >> 5) == 0) TCGEN05_DEALLOC(tmem, 512);
    CLUSTER_SYNC();   // no CTA exits while peers' multicasts may target its smem
#endif // HAS_TCGEN05
}

// ================= tensor-core attention (fp16 operands, __expf) =============
#define AT_SMEM_TOTAL 51200
#define AT_P(s)   (2048 + (s) * 16384)
#define AT_V(s)   (34816 + (s) * 8192)
#define AT_IDESC  ((1u << 4) | (8u << 17) | (8u << 24))   // f16, N=64, M=128

__global__ void __launch_bounds__(256)
attn_kernel(const float* __restrict__ qs, const float* __restrict__ ks,
            const __half* __restrict__ v, const unsigned char* __restrict__ mask,
            const float4* __restrict__ kstat, __half* __restrict__ pool)
{
#if HAS_TCGEN05
    extern __shared__ char sm[];
    const uint32_t sb = smem_to_u32(sm);
    float* lsum = (float*)(sm + 64);
    float* ksm  = (float*)(sm + 1088);
    unsigned* mbits = (unsigned*)(sm + 1344);

    const int tx = threadIdx.x;
    const int bh = blockIdx.y;
    const int b  = bh >> 4;
    const int h  = bh & 15;
    const int m0 = blockIdx.x << 7;

    const int q     = tx & 127;
    const int nhalf = tx >> 7;
    const int q7    = q & 7;

    if ((tx >> 5) == 0) TCGEN05_ALLOC(sb, 64);
    if (tx == 0) { MBARRIER_INIT(sb + 8, 1); MBARRIER_INIT(sb + 16, 1); }
    __syncthreads();
    if ((tx >> 5) == 0) TCGEN05_RELINQUISH();
    uint32_t tmem;
    asm volatile("ld.shared.b32 %0, [%1];" : "=r"(tmem) : "r"(sb));

    const float qv = qs[((size_t)(m0 + q) * BATCH + b) * NHEAD + h];
    const float4 kst = kstat[bh];
    float mu = (kst.w > 0.f) ? fmaxf(qv * kst.x, qv * kst.y) : -1e30f;
    const float mq = (kst.z > 0.f) ? fmaxf(mu, -1000.0f) : mu;

    float lpart = 0.f;
    int dph0 = 0, dph1 = 0;

    const int vn = tx >> 2;             // 0..63
    const int dq = (tx & 3) << 4;       // 0,16,32,48

    for (int i = 0; i < 16; i++) {
        const int s  = i & 1;
        const int n0 = i << 6;
        if (i >= 2) {
            if (s == 0) { MBAR_WAIT(sb + 8,  dph0); dph0 ^= 1; }
            else        { MBAR_WAIT(sb + 16, dph1); dph1 ^= 1; }
        }

        if (tx < 64) {
            ksm[tx] = ks[((size_t)(n0 + tx) * BATCH + b) * NHEAD + h];
            const bool mm = mask[(size_t)(n0 + tx) * BATCH + b] != 0;
            const unsigned bal = __ballot_sync(0xffffffffu, mm);
            if ((tx & 31) == 0) mbits[tx >> 5] = bal;
        }

        // V tile transpose
        {
            const __half* vp = v + ((size_t)(n0 + vn) * BATCH + b) * D_MODEL + h * DHEAD + dq;
            const uint4 va = *(const uint4*)vp;
            const uint4 vb_ = *(const uint4*)(vp + 8);
            const __half* h0 = (const __half*)&va;
            const __half* h1 = (const __half*)&vb_;
            char* vtb = sm + AT_V(s);
            const int nblk = vn >> 3;
            const int nrem = (vn & 7) << 1;
            #pragma unroll
            for (int e = 0; e < 8; e++) {
                const int d = dq + e;
                *(__half*)(vtb + d * 128 + ((nblk ^ (d & 7)) << 4) + nrem) = h0[e];
            }
            #pragma unroll
            for (int e = 0; e < 8; e++) {
                const int d = dq + 8 + e;
                *(__half*)(vtb + d * 128 + ((nblk ^ (d & 7)) << 4) + nrem) = h1[e];
            }
        }
        __syncthreads();

        // P compute: 32 exps per thread -> fp16 swizzled STS
        {
            const unsigned mb = mbits[nhalf];
            char* pb = sm + AT_P(s) + q * 128;
            #pragma unroll
            for (int g = 0; g < 4; g++) {
                __half ph[8];
                #pragma unroll
                for (int e = 0; e < 8; e++) {
                    const int np_ = g * 8 + e;
                    const float kv = ksm[nhalf * 32 + np_];
                    const float sc = ((mb >> np_) & 1u) ? -1000.0f : qv * kv;
                    ph[e] = __float2half_rn(__expf(sc - mq));
                    lpart += __half2float(ph[e]);
                }
                *(uint4*)(pb + (((nhalf * 4 + g) ^ q7) << 4)) = *(const uint4*)ph;
            }
        }
        FENCE_PROXY_ASYNC();
        __syncthreads();

        if (tx == 0) {
            TC_FENCE_AFTER();
            const uint64_t pd = MAKE_SMEM_DESC(sb + AT_P(s));
            const uint64_t vd = MAKE_SMEM_DESC(sb + AT_V(s));
            #pragma unroll
            for (int k8 = 0; k8 < 4; k8++)
                mma_f16_ss(tmem, pd + 2 * k8, vd + 2 * k8, AT_IDESC, (i | k8) ? 1u : 0u);
            TC_COMMIT(sb + 8 + s * 8);
        }
    }

    MBAR_WAIT(sb + 8,  dph0);
    MBAR_WAIT(sb + 16, dph1);
    lsum[tx] = lpart;
    __syncthreads();
    TC_FENCE_AFTER();

    const int w = tx >> 5;
    if (w < 4) {
        const int lane = tx & 31;
        const int ql   = w * 32 + lane;
        uint32_t d[64];
        TCGEN05_LD_32X32B_X32(d,      tmem);
        TCGEN05_LD_32X32B_X32(d + 32, tmem + 32);
        TCGEN05_WAIT_LD();

        const float inv = 1.f / (lsum[ql] + lsum[ql + 128]);
        const int row = (m0 + ql) * BATCH + b;
        const int rw7 = row & 7;
        #pragma unroll
        for (int jg = 0; jg < 16; jg++) {
            const int col = h * 64 + jg * 4;
            const __half2 h01 = __floats2half2_rn(__uint_as_float(d[jg * 4 + 0]) * inv,
                                                  __uint_as_float(d[jg * 4 + 1]) * inv);
            const __half2 h23 = __floats2half2_rn(__uint_as_float(d[jg * 4 + 2]) * inv,
                                                  __uint_as_float(d[jg * 4 + 3]) * inv);
            const size_t oidx = ((size_t)(col >> 6) * M_TOK + row) * 64 +
                                ((((col >> 3) & 7) ^ rw7) << 3) + (col & 7);
            __half2* dst = (__half2*)(pool + oidx);
            dst[0] = h01; dst[1] = h23;
        }
    }

    __syncthreads();
    if ((tx >> 5) == 0) TCGEN05_DEALLOC(tmem, 64);
#endif // HAS_TCGEN05
}

// ---------------- launcher (serial, single stream) ---------------------------
extern "C" void kernel_launch(void* const* d_in, const int* in_sizes, int n_in,
                              void* d_out, int out_size)
{
    const float* x     = (const float*)d_in[0];
    const unsigned char* mask = (const unsigned char*)d_in[1];
    const float* ln1_g = (const float*)d_in[2];
    const float* ln1_b = (const float*)d_in[3];
    const float* wq    = (const float*)d_in[4];
    const float* bq    = (const float*)d_in[5];
    const float* wk    = (const float*)d_in[6];
    const float* bk    = (const float*)d_in[7];
    const float* wv    = (const float*)d_in[8];
    const float* bv    = (const float*)d_in[9];
    const float* wo    = (const float*)d_in[10];
    const float* bo    = (const float*)d_in[11];
    const float* ln2_g = (const float*)d_in[12];
    const float* ln2_b = (const float*)d_in[13];
    const float* w1    = (const float*)d_in[14];
    const float* b1    = (const float*)d_in[15];
    const float* w2    = (const float*)d_in[16];
    const float* b2    = (const float*)d_in[17];
    float* out = (float*)d_out;

    float* scratch = nullptr;
    cudaGetSymbolAddress((void**)&scratch, g_scratch);
    __half* xn   = (__half*)(scratch + OFF_XN);
    __half* vbuf = (__half*)(scratch + OFF_V);
    __half* pool = (__half*)(scratch + OFF_POOL);
    float*  x2   = scratch + OFF_X2;
    __half* hbuf = (__half*)(scratch + OFF_H);
    float*  qsb  = scratch + OFF_QS;
    float*  ksb  = scratch + OFF_KS;
    float*  wqk  = scratch + OFF_WQK;
    float*  bqk  = scratch + OFF_BQK;
    __half* wvt  = (__half*)(scratch + OFF_WVT);
    __half* wot  = (__half*)(scratch + OFF_WOT);
    __half* w1t  = (__half*)(scratch + OFF_W1T);
    __half* w2t  = (__half*)(scratch + OFF_W2T);
    float4* kstat = (float4*)(scratch + OFF_KSTAT);

    cudaFuncSetAttribute(sgemm_tc<false, false, 2>, cudaFuncAttributeMaxDynamicSharedMemorySize, TC_SMEM_TOTAL);
    cudaFuncSetAttribute(sgemm_tc<false, true,  0>, cudaFuncAttributeMaxDynamicSharedMemorySize, TC_SMEM_TOTAL);
    cudaFuncSetAttribute(sgemm_tc<true,  false, 1>, cudaFuncAttributeMaxDynamicSharedMemorySize, TC_SMEM_TOTAL);
    cudaFuncSetAttribute(attn_kernel, cudaFuncAttributeMaxDynamicSharedMemorySize, AT_SMEM_TOTAL);

    // 0. weight prep: merged transposes + head sums
    transpose_all<<<10240, 256>>>(wv, wo, w1, w2, wvt, wot, w1t, w2t);
    headsum_kernel<<<64, 256>>>(wq, bq, wk, bk, wqk, bqk);
    // 1. xn = LN1(x)  (chunked fp16)
    ln_kernel<<<M_TOK, 256>>>(x, ln1_g, ln1_b, xn);
    // 2. v = xn @ wv + bv   (fp16 row-major out)
    sgemm_tc<false, false, 2><<<dim3(D_MODEL / 256, M_TOK / 256), 256, TC_SMEM_TOTAL>>>(
        xn, wvt, bv, nullptr, vbuf, D_MODEL, D_MODEL);
    // 3. qs/ks = xn @ wqk + bqk
    qsks_gemm<<<M_TOK / 32, 256>>>(xn, wqk, bqk, qsb, ksb);
    // 4. key stats for closed-form softmax max
    kminmax_kernel<<<BATCH * NHEAD, 256>>>(ksb, mask, kstat);
    // 5. pooled = softmax(qs ⊗ ks, masked) @ v   (chunked fp16 out)
    attn_kernel<<<dim3(SEQ / 128, BATCH * NHEAD), 256, AT_SMEM_TOTAL>>>(
        qsb, ksb, vbuf, mask, kstat, pool);
    // 6. x2 = pooled @ wo + bo + x   (fp32 row out)
    sgemm_tc<false, true, 0><<<dim3(D_MODEL / 256, M_TOK / 256), 256, TC_SMEM_TOTAL>>>(
        pool, wot, bo, x, x2, D_MODEL, D_MODEL);
    // 7. xn = LN2(x2)
    ln_kernel<<<M_TOK, 256>>>(x2, ln2_g, ln2_b, xn);
    // 8. h = relu(xn @ w1 + b1)   (chunked fp16 out)
    sgemm_tc<true, false, 1><<<dim3(FF_DIM / 256, M_TOK / 256), 256, TC_SMEM_TOTAL>>>(
        xn, w1t, b1, nullptr, hbuf, FF_DIM, D_MODEL);
    // 9. out = h @ w2 + b2 + x2
    sgemm_tc<false, true, 0><<<dim3(D_MODEL / 256, M_TOK / 256), 256, TC_SMEM_TOTAL>>>(
        hbuf, w2t, b2, x2, out, D_MODEL, FF_DIM);
}

// round 16
// speedup vs baseline: 1.0466x; 1.0466x over previous
#include <cuda_runtime.h>
#include <cuda_fp16.h>
#include <cstddef>
#include <cstdint>

// Problem constants
#define M_TOK   8192     // M*B token rows
#define D_MODEL 1024
#define FF_DIM  4096
#define NHEAD   16
#define DHEAD   64
#define SEQ     1024
#define BATCH   8

// tcgen05 is arch-SPECIFIC (sm_103a). nvcc also runs a generic compute_103 PTX
// pass where these instructions don't exist — compile a stub there.
#if defined(__CUDA_ARCH__) && (defined(__CUDA_ARCH_FEAT_SM103_ALL) || defined(__CUDA_ARCH_SPECIFIC__))
#define HAS_TCGEN05 1
#else
#define HAS_TCGEN05 0
#endif

// ---------------- tcgen05 / TMA helpers ----------------
static constexpr uint64_t SMEM_DESC_BASE_SW128 =
    (uint64_t(2)  << 61) | (uint64_t(1) << 46) | (uint64_t(64) << 32) | (uint64_t(1) << 16);
#define MAKE_SMEM_DESC(base_addr) \
    (SMEM_DESC_BASE_SW128 | ((uint64_t)((base_addr) >> 4) & 0x3FFF))

__device__ __forceinline__ uint32_t smem_to_u32(const void* p) {
    uint32_t a;
    asm("{ .reg .u64 t; cvta.to.shared.u64 t, %1; cvt.u32.u64 %0, t; }" : "=r"(a) : "l"(p));
    return a;
}

#if HAS_TCGEN05
#define TCGEN05_ALLOC(smem_res, nCols) \
    asm volatile("tcgen05.alloc.cta_group::1.sync.aligned.shared::cta.b32 [%0], %1;" \
                 :: "r"((uint32_t)(smem_res)), "r"((uint32_t)(nCols)) : "memory")
#define TCGEN05_DEALLOC(tmem, nCols) \
    asm volatile("tcgen05.dealloc.cta_group::1.sync.aligned.b32 %0, %1;" \
                 :: "r"(tmem), "r"((uint32_t)(nCols)))
#define TCGEN05_RELINQUISH() \
    asm volatile("tcgen05.relinquish_alloc_permit.cta_group::1.sync.aligned;")
#define TCGEN05_WAIT_LD() asm volatile("tcgen05.wait::ld.sync.aligned;" ::: "memory")
#define TC_FENCE_AFTER()  asm volatile("tcgen05.fence::after_thread_sync;" ::: "memory")
#define TC_COMMIT(mbar) \
    asm volatile("tcgen05.commit.cta_group::1.mbarrier::arrive::one.shared::cluster.b64 [%0];" \
                 :: "r"((uint32_t)(mbar)) : "memory")
#endif

#define FENCE_PROXY_ASYNC() asm volatile("fence.proxy.async.shared::cta;" ::: "memory")
#define MBARRIER_INIT(mbar, cnt) \
    asm volatile("mbarrier.init.shared.b64 [%0], %1;" :: "r"((uint32_t)(mbar)), "r"((uint32_t)(cnt)) : "memory")
#define MBARRIER_EXPECT_TX(mbar, bytes) \
    asm volatile("mbarrier.arrive.expect_tx.shared.b64 _, [%0], %1;" \
                 :: "r"((uint32_t)(mbar)), "r"((uint32_t)(bytes)) : "memory")
#define MBARRIER_ARRIVE(mbar) \
    asm volatile("mbarrier.arrive.shared.b64 _, [%0];" :: "r"((uint32_t)(mbar)) : "memory")
#define MBAR_WAIT(mbar, ph) \
    asm volatile("{\n\t.reg .pred P;\n\tWL%=:\n\t" \
                 "mbarrier.try_wait.parity.acquire.cta.shared::cta.b64 P, [%0], %1, 0x989680;\n\t" \
                 "@!P bra WL%=;\n\t}" :: "r"((uint32_t)(mbar)), "r"((uint32_t)(ph)) : "memory")
#define BULK_G2S(dst, src, bytes, mbar) \
    asm volatile("cp.async.bulk.shared::cta.global.mbarrier::complete_tx::bytes [%0], [%1], %2, [%3];" \
                 :: "r"((uint32_t)(dst)), "l"(src), "r"((uint32_t)(bytes)), "r"((uint32_t)(mbar)) : "memory")

#if HAS_TCGEN05
#define TCGEN05_LD_32X32B_X32(r, tmem_addr) \
    asm volatile( \
        "tcgen05.ld.sync.aligned.32x32b.x32.b32 " \
        "{%0, %1, %2, %3, %4, %5, %6, %7, " \
        " %8, %9, %10, %11, %12, %13, %14, %15, " \
        " %16, %17, %18, %19, %20, %21, %22, %23, " \
        " %24, %25, %26, %27, %28, %29, %30, %31}, [%32];" \
        : "=r"((r)[0]),  "=r"((r)[1]),  "=r"((r)[2]),  "=r"((r)[3]), \
          "=r"((r)[4]),  "=r"((r)[5]),  "=r"((r)[6]),  "=r"((r)[7]), \
          "=r"((r)[8]),  "=r"((r)[9]),  "=r"((r)[10]), "=r"((r)[11]), \
          "=r"((r)[12]), "=r"((r)[13]), "=r"((r)[14]), "=r"((r)[15]), \
          "=r"((r)[16]), "=r"((r)[17]), "=r"((r)[18]), "=r"((r)[19]), \
          "=r"((r)[20]), "=r"((r)[21]), "=r"((r)[22]), "=r"((r)[23]), \
          "=r"((r)[24]), "=r"((r)[25]), "=r"((r)[26]), "=r"((r)[27]), \
          "=r"((r)[28]), "=r"((r)[29]), "=r"((r)[30]), "=r"((r)[31]) \
        : "r"(tmem_addr))

// f16 SS MMA, cg1. idesc: dtype F32(1<<4) | atype F16(0) | btype F16(0)
//                        | (N/8)<<17 | (M/16)<<24
__device__ __forceinline__ void mma_f16_ss(uint32_t d_tmem, uint64_t a_desc, uint64_t b_desc,
                                           uint32_t idesc, uint32_t en)
{
    asm volatile(
        "{\n\t"
        ".reg .pred p;\n\t"
        "setp.ne.u32 p, %5, 0;\n\t"
        "tcgen05.mma.cta_group::1.kind::f16 [%0], %1, %2, %3, {%4, %4, %4, %4}, p;\n\t"
        "}"
        :: "r"(d_tmem), "l"(a_desc), "l"(b_desc), "r"(idesc), "r"(0u), "r"(en)
        : "memory");
}
#endif

// ============ chunked + pre-swizzled fp16 GEMM operand layout =================
__device__ __forceinline__ size_t hchunk_idx(int row, int k, int R) {
    return ((size_t)(k >> 6) * R + row) * 64 + ((((k >> 3) & 7) ^ (row & 7)) << 3) + (k & 7);
}

// ---------------- scratch (static device memory; float-array backing) --------
static const size_t OFF_XN    = 0;          // half [16][8192][64]
static const size_t OFF_V     = 4194304;    // half row-major [8192][1024]
static const size_t OFF_POOL  = 8388608;    // half chunked
static const size_t OFF_X2    = 12582912;   // fp32 [8192][1024]
static const size_t OFF_H     = 20971520;   // half chunked [64][8192][64]
static const size_t OFF_QS    = 37748736;
static const size_t OFF_KS    = 37879808;
static const size_t OFF_WQK   = 38010880;   // fp32 [1024][32]
static const size_t OFF_BQK   = 38043648;
static const size_t OFF_WVT   = 38043680;   // half chunked
static const size_t OFF_WOT   = 38567968;
static const size_t OFF_W1T   = 39092256;
static const size_t OFF_W2T   = 41189408;
static const size_t OFF_KSTAT = 43286560;
static const size_t SCRATCH_FLOATS = 43287072;

__device__ float g_scratch[SCRATCH_FLOATS];

// ---------------- LayerNorm: row-major fp32 in -> chunked fp16 out ----------
__global__ void __launch_bounds__(256)
ln_kernel(const float* __restrict__ x, const float* __restrict__ g,
          const float* __restrict__ bta, __half* __restrict__ y)
{
    const int row = blockIdx.x;
    const int tx  = threadIdx.x;
    const float4 v = ((const float4*)(x + (size_t)row * D_MODEL))[tx];

    float s  = v.x + v.y + v.z + v.w;
    float sq = v.x * v.x + v.y * v.y + v.z * v.z + v.w * v.w;
    #pragma unroll
    for (int o = 16; o; o >>= 1) {
        s  += __shfl_xor_sync(0xffffffffu, s,  o);
        sq += __shfl_xor_sync(0xffffffffu, sq, o);
    }
    __shared__ float ss[8], ssq[8];
    const int w = tx >> 5, l = tx & 31;
    if (l == 0) { ss[w] = s; ssq[w] = sq; }
    __syncthreads();
    s = 0.f; sq = 0.f;
    #pragma unroll
    for (int i = 0; i < 8; i++) { s += ss[i]; sq += ssq[i]; }

    const float mean = s * (1.f / D_MODEL);
    const float var  = sq * (1.f / D_MODEL) - mean * mean;
    const float rstd = rsqrtf(var + 1e-5f);

    const float4 gv = ((const float4*)g)[tx];
    const float4 bv = ((const float4*)bta)[tx];
    const __half2 h01 = __floats2half2_rn((v.x - mean) * rstd * gv.x + bv.x,
                                          (v.y - mean) * rstd * gv.y + bv.y);
    const __half2 h23 = __floats2half2_rn((v.z - mean) * rstd * gv.z + bv.z,
                                          (v.w - mean) * rstd * gv.w + bv.w);
    const size_t oidx = ((size_t)(tx >> 4) * M_TOK + row) * 64 +
                        ((((tx >> 1) & 7) ^ (row & 7)) << 3) + ((tx & 1) << 2);
    __half2* dst = (__half2*)(y + oidx);
    dst[0] = h01; dst[1] = h23;
}

// ---------------- merged transpose: all 4 weights -> chunked fp16 -----------
__global__ void __launch_bounds__(256)
transpose_all(const float* __restrict__ wv, const float* __restrict__ wo,
              const float* __restrict__ w1, const float* __restrict__ w2,
              __half* __restrict__ wvt, __half* __restrict__ wot,
              __half* __restrict__ w1t, __half* __restrict__ w2t)
{
    int bid = blockIdx.x;
    const float* in; __half* out; int N;
    if (bid < 1024)      { in = wv; out = wvt; N = 1024; }
    else if (bid < 2048) { bid -= 1024; in = wo; out = wot; N = 1024; }
    else if (bid < 6144) { bid -= 2048; in = w1; out = w1t; N = 4096; }
    else                 { bid -= 6144; in = w2; out = w2t; N = 1024; }
    const int nbx = N >> 5;
    const int n0 = (bid % nbx) << 5;
    const int k0 = (bid / nbx) << 5;

    __shared__ float t[32][33];
    const int tx = threadIdx.x & 31;
    const int ty = threadIdx.x >> 5;   // 0..7
    #pragma unroll
    for (int i = 0; i < 4; i++)
        t[ty + (i << 3)][tx] = in[(size_t)(k0 + ty + (i << 3)) * N + n0 + tx];
    __syncthreads();
    #pragma unroll
    for (int i = 0; i < 4; i++) {
        const int n = n0 + ty + (i << 3);
        const int k = k0 + tx;
        out[hchunk_idx(n, k, N)] = __float2half_rn(t[tx][ty + (i << 3)]);
    }
}

// ---------------- head-sum of wq/wk columns into combined [1024][32] ---------
__global__ void headsum_kernel(const float* __restrict__ wq, const float* __restrict__ bq,
                               const float* __restrict__ wk, const float* __restrict__ bk,
                               float* __restrict__ wqk, float* __restrict__ bqk)
{
    const int idx = blockIdx.x * blockDim.x + threadIdx.x;
    if (idx < D_MODEL * NHEAD) {
        const int d = idx >> 4, h = idx & 15;
        const float* pq = wq + (size_t)d * D_MODEL + h * DHEAD;
        const float* pk = wk + (size_t)d * D_MODEL + h * DHEAD;
        float sq = 0.f, sk = 0.f;
        #pragma unroll 8
        for (int i = 0; i < DHEAD; i++) { sq += pq[i]; sk += pk[i]; }
        wqk[d * 32 + h]      = sq;
        wqk[d * 32 + 16 + h] = sk;
    }
    if (idx < NHEAD) {
        float sq = 0.f, sk = 0.f;
        for (int i = 0; i < DHEAD; i++) {
            sq += bq[idx * DHEAD + i];
            sk += bk[idx * DHEAD + i];
        }
        bqk[idx] = sq; bqk[16 + idx] = sk;
    }
}

// ---------------- skinny GEMM v3: 256 blocks x 32 rows -----------------------
__global__ void __launch_bounds__(256)
qsks_gemm(const __half* __restrict__ xn, const float* __restrict__ wqk,
          const float* __restrict__ bqk, float* __restrict__ qs, float* __restrict__ ks)
{
    __shared__ __half Araw[2048];     // 32 rows x 64 halves = 256 uint4
    __shared__ float Wsm[64][36];

    const int tx = threadIdx.x;
    const int r  = tx >> 3;           // 0..31
    const int cg = tx & 7;
    const int brow = blockIdx.x << 5;
    const int p7 = r & 7;

    float acc[4];
    #pragma unroll
    for (int j = 0; j < 4; j++) acc[j] = 0.f;

    for (int chk = 0; chk < 16; chk++) {
        {
            const uint4* src = (const uint4*)(xn + ((size_t)chk * M_TOK + brow) * 64);
            ((uint4*)Araw)[tx] = src[tx];
        }
        {
            const int row = tx >> 3, c4 = (tx & 7) << 2;
            *(float4*)&Wsm[row][c4]      = *(const float4*)(wqk + (size_t)(chk * 64 + row) * 32 + c4);
            *(float4*)&Wsm[row + 32][c4] = *(const float4*)(wqk + (size_t)(chk * 64 + row + 32) * 32 + c4);
        }
        __syncthreads();

        #pragma unroll
        for (int j = 0; j < 8; j++) {
            const uint4 ab = *(const uint4*)&Araw[r * 64 + ((j ^ p7) << 3)];
            const __half2* hp = (const __half2*)&ab;
            #pragma unroll
            for (int e = 0; e < 4; e++) {
                const float2 f2 = __half22float2(hp[e]);
                const int kk = j * 8 + e * 2;
                {
                    const float4 w0 = *(const float4*)&Wsm[kk][cg * 4];
                    acc[0] = fmaf(f2.x, w0.x, acc[0]); acc[1] = fmaf(f2.x, w0.y, acc[1]);
                    acc[2] = fmaf(f2.x, w0.z, acc[2]); acc[3] = fmaf(f2.x, w0.w, acc[3]);
                }
                {
                    const float4 w0 = *(const float4*)&Wsm[kk + 1][cg * 4];
                    acc[0] = fmaf(f2.y, w0.x, acc[0]); acc[1] = fmaf(f2.y, w0.y, acc[1]);
                    acc[2] = fmaf(f2.y, w0.z, acc[2]); acc[3] = fmaf(f2.y, w0.w, acc[3]);
                }
            }
        }
        __syncthreads();
    }

    const size_t row = (size_t)(brow + r);
    #pragma unroll
    for (int j = 0; j < 4; j++) {
        const int c = cg * 4 + j;
        const float v = acc[j] + bqk[c];
        if (c < 16) qs[row * NHEAD + c]        = v;
        else        ks[row * NHEAD + (c - 16)] = v;
    }
}

// ---------------- per-(b,h) key stats ----------------------------------------
__global__ void __launch_bounds__(256)
kminmax_kernel(const float* __restrict__ ks, const unsigned char* __restrict__ mask,
               float4* __restrict__ kstat)
{
    const int bh = blockIdx.x;
    const int b  = bh >> 4;
    const int h  = bh & 15;
    const int tx = threadIdx.x;

    float kmx = -1e30f, kmn = 1e30f;
    int cnt = 0, anym = 0;
    for (int n = tx; n < SEQ; n += 256) {
        const float kv = ks[((size_t)n * BATCH + b) * NHEAD + h];
        if (mask[(size_t)n * BATCH + b]) anym = 1;
        else { kmx = fmaxf(kmx, kv); kmn = fminf(kmn, kv); cnt++; }
    }
    __shared__ float smx[256], smn[256];
    __shared__ int scnt[256], sany[256];
    smx[tx] = kmx; smn[tx] = kmn; scnt[tx] = cnt; sany[tx] = anym;
    __syncthreads();
    for (int o = 128; o; o >>= 1) {
        if (tx < o) {
            smx[tx] = fmaxf(smx[tx], smx[tx + o]);
            smn[tx] = fminf(smn[tx], smn[tx + o]);
            scnt[tx] += scnt[tx + o];
            sany[tx] |= sany[tx + o];
        }
        __syncthreads();
    }
    if (tx == 0)
        kstat[bh] = make_float4(smx[0], smn[0], sany[0] ? 1.f : 0.f, (float)scnt[0]);
}

// ======== persistent tcgen05 f16 GEMM: 256x256 tiles, warp-specialized =========
// Grid fixed at 128 CTAs; each CTA loops tiles t = bid + 128*it (ntile % 128 == 0).
// Warp 8 (tx 256) = consumer/MMA; warp 9 (tx 288) = producer/TMA; warps 0-7 =
// per-tile epilogue. Producer keeps filling the 3-stage ring across tile
// boundaries; consumer waits epi_done before reusing the (single) TMEM buffer.
#define TC_STAGES   3
#define TC_HDR      1024
#define TC_STAGE_SZ 65536
#define TC_SMEM_TOTAL (TC_HDR + TC_STAGES * TC_STAGE_SZ)   // 197632
#define TC_IDESC  ((1u << 4) | (32u << 17) | (8u << 24))   // f16, N=256, M=128
#define TC_GRID   128
#define TC_THREADS 320
// mbarrier layout: full[s]@8+8s  done[s]@32+8s  epi_full@56  epi_done@64

template<bool RELU, bool RESID, int OUTMODE>
__global__ void __launch_bounds__(TC_THREADS)
sgemm_tc(const __half* __restrict__ A, const __half* __restrict__ Wt,
         const float* __restrict__ bias, const float* __restrict__ resid,
         void* __restrict__ C, int N, int K)
{
#if HAS_TCGEN05
    extern __shared__ char sm[];
    const uint32_t sb = smem_to_u32(sm);
    const int tx = threadIdx.x;
    const int nN     = N >> 8;                   // N tiles
    const int niter  = ((M_TOK >> 8) * nN) >> 7; // tiles per CTA (1 or 4)
    const int nchunk = K >> 6;

    if ((tx >> 5) == 0) TCGEN05_ALLOC(sb, 512);
    if (tx == 0) {
        #pragma unroll
        for (int s = 0; s < TC_STAGES; s++) {
            MBARRIER_INIT(sb + 8 + s * 8, 1);    // full[s]
            MBARRIER_INIT(sb + 32 + s * 8, 1);   // done[s]
        }
        MBARRIER_INIT(sb + 56, 1);               // epi_full (per tile)
        MBARRIER_INIT(sb + 64, 8);               // epi_done (8 epilogue warps)
    }
    __syncthreads();
    if ((tx >> 5) == 0) TCGEN05_RELINQUISH();
    uint32_t tmem;
    asm volatile("ld.shared.b32 %0, [%1];" : "=r"(tmem) : "r"(sb));

    if (tx == 256) {
        // ---- consumer (warp 8): MMA issuer ----
        TC_FENCE_AFTER();
        int phF0 = 0, phF1 = 0, phF2 = 0;
        int g = 0;
        for (int it = 0; it < niter; it++) {
            if (it > 0) MBAR_WAIT(sb + 64, (it - 1) & 1);   // epilogue freed TMEM
            for (int c = 0; c < nchunk; c++, g++) {
                const int s = g % TC_STAGES;
                int ph;
                if (s == 0)      { ph = phF0; phF0 ^= 1; }
                else if (s == 1) { ph = phF1; phF1 ^= 1; }
                else             { ph = phF2; phF2 ^= 1; }
                MBAR_WAIT(sb + 8 + s * 8, ph);
                const uint32_t abase = sb + TC_HDR + s * TC_STAGE_SZ;
                const uint64_t ad0 = MAKE_SMEM_DESC(abase);
                const uint64_t ad1 = MAKE_SMEM_DESC(abase + 16384);
                const uint64_t bd  = MAKE_SMEM_DESC(abase + 32768);
                #pragma unroll
                for (int k8 = 0; k8 < 4; k8++) {
                    const uint32_t en = (c | k8) ? 1u : 0u;
                    mma_f16_ss(tmem,       ad0 + 2 * k8, bd + 2 * k8, TC_IDESC, en);
                    mma_f16_ss(tmem + 256, ad1 + 2 * k8, bd + 2 * k8, TC_IDESC, en);
                }
                TC_COMMIT(sb + 32 + s * 8);
            }
            TC_COMMIT(sb + 56);   // epi_full: fires when this tile's MMAs complete
        }
    } else if (tx == 288) {
        // ---- producer (warp 9): TMA fills, gated only by ring slots ----
        int phD0 = 0, phD1 = 0, phD2 = 0;
        int g = 0;
        for (int it = 0; it < niter; it++) {
            const int t = blockIdx.x + (it << 7);
            const int brow = (t / nN) << 8;
            const int bcol = (t % nN) << 8;
            for (int c = 0; c < nchunk; c++, g++) {
                const int s = g % TC_STAGES;
                if (g >= TC_STAGES) {
                    int ph;
                    if (s == 0)      { ph = phD0; phD0 ^= 1; }
                    else if (s == 1) { ph = phD1; phD1 ^= 1; }
                    else             { ph = phD2; phD2 ^= 1; }
                    MBAR_WAIT(sb + 32 + s * 8, ph);
                }
                const uint32_t abase = sb + TC_HDR + s * TC_STAGE_SZ;
                const uint32_t full = sb + 8 + s * 8;
                MBARRIER_EXPECT_TX(full, 2 * 32768);
                BULK_G2S(abase,         A + ((size_t)c * M_TOK + brow) * 64, 32768, full);
                BULK_G2S(abase + 32768, Wt + ((size_t)c * N + bcol) * 64, 32768, full);
            }
        }
    } else if (tx < 256) {
        // ---- epilogue (warps 0-7): per tile, read TMEM + store ----
        const int w     = tx >> 5;
        const int lane  = tx & 31;
        const int mtile = w >> 2;
        for (int it = 0; it < niter; it++) {
            const int t = blockIdx.x + (it << 7);
            const int brow = (t / nN) << 8;
            const int bcol = (t % nN) << 8;
            MBAR_WAIT(sb + 56, it & 1);
            TC_FENCE_AFTER();
            const int row = brow + (mtile << 7) + ((w & 3) << 5) + lane;
            const int rw7 = row & 7;
            #pragma unroll
            for (int slab = 0; slab < 4; slab++) {
                uint32_t d[64];
                TCGEN05_LD_32X32B_X32(d,      tmem + mtile * 256 + slab * 64);
                TCGEN05_LD_32X32B_X32(d + 32, tmem + mtile * 256 + slab * 64 + 32);
                TCGEN05_WAIT_LD();
                if (slab == 3 && lane == 0) MBARRIER_ARRIVE(sb + 64);  // TMEM free
                const int cb = bcol + slab * 64;
                const float* bp = bias + cb;
                const float* rp = RESID ? (resid + (size_t)row * N + cb) : nullptr;
                #pragma unroll
                for (int j = 0; j < 64; j += 4) {
                    const float4 bv = *(const float4*)(bp + j);
                    float4 o;
                    o.x = __uint_as_float(d[j + 0]) + bv.x;
                    o.y = __uint_as_float(d[j + 1]) + bv.y;
                    o.z = __uint_as_float(d[j + 2]) + bv.z;
                    o.w = __uint_as_float(d[j + 3]) + bv.w;
                    if (RESID) {
                        const float4 rv = *(const float4*)(rp + j);
                        o.x += rv.x; o.y += rv.y; o.z += rv.z; o.w += rv.w;
                    }
                    if (RELU) {
                        o.x = fmaxf(o.x, 0.f); o.y = fmaxf(o.y, 0.f);
                        o.z = fmaxf(o.z, 0.f); o.w = fmaxf(o.w, 0.f);
                    }
                    if (OUTMODE == 1) {
                        const int col = cb + j;
                        const __half2 h01 = __floats2half2_rn(o.x, o.y);
                        const __half2 h23 = __floats2half2_rn(o.z, o.w);
                        const size_t oidx = ((size_t)(col >> 6) * M_TOK + row) * 64 +
                                            ((((col >> 3) & 7) ^ rw7) << 3) + (col & 7);
                        __half2* dst = (__half2*)((__half*)C + oidx);
                        dst[0] = h01; dst[1] = h23;
                    } else if (OUTMODE == 2) {
                        const __half2 h01 = __floats2half2_rn(o.x, o.y);
                        const __half2 h23 = __floats2half2_rn(o.z, o.w);
                        __half2* dst = (__half2*)((__half*)C + (size_t)row * N + cb + j);
                        dst[0] = h01; dst[1] = h23;
                    } else {
                        *(float4*)((float*)C + (size_t)row * N + cb + j) = o;
                    }
                }
            }
        }
    }
    __syncthreads();
    if ((tx >> 5) == 0) TCGEN05_DEALLOC(tmem, 512);
#endif // HAS_TCGEN05
}

// ================= tensor-core attention (fp16 operands, __expf) =============
#define AT_SMEM_TOTAL 51200
#define AT_P(s)   (2048 + (s) * 16384)
#define AT_V(s)   (34816 + (s) * 8192)
#define AT_IDESC  ((1u << 4) | (8u << 17) | (8u << 24))   // f16, N=64, M=128

__global__ void __launch_bounds__(256)
attn_kernel(const float* __restrict__ qs, const float* __restrict__ ks,
            const __half* __restrict__ v, const unsigned char* __restrict__ mask,
            const float4* __restrict__ kstat, __half* __restrict__ pool)
{
#if HAS_TCGEN05
    extern __shared__ char sm[];
    const uint32_t sb = smem_to_u32(sm);
    float* lsum = (float*)(sm + 64);
    float* ksm  = (float*)(sm + 1088);
    unsigned* mbits = (unsigned*)(sm + 1344);

    const int tx = threadIdx.x;
    const int bh = blockIdx.y;
    const int b  = bh >> 4;
    const int h  = bh & 15;
    const int m0 = blockIdx.x << 7;

    const int q     = tx & 127;
    const int nhalf = tx >> 7;
    const int q7    = q & 7;

    if ((tx >> 5) == 0) TCGEN05_ALLOC(sb, 64);
    if (tx == 0) { MBARRIER_INIT(sb + 8, 1); MBARRIER_INIT(sb + 16, 1); }
    __syncthreads();
    if ((tx >> 5) == 0) TCGEN05_RELINQUISH();
    uint32_t tmem;
    asm volatile("ld.shared.b32 %0, [%1];" : "=r"(tmem) : "r"(sb));

    const float qv = qs[((size_t)(m0 + q) * BATCH + b) * NHEAD + h];
    const float4 kst = kstat[bh];
    float mu = (kst.w > 0.f) ? fmaxf(qv * kst.x, qv * kst.y) : -1e30f;
    const float mq = (kst.z > 0.f) ? fmaxf(mu, -1000.0f) : mu;

    float lpart = 0.f;
    int dph0 = 0, dph1 = 0;

    const int vn = tx >> 2;             // 0..63
    const int dq = (tx & 3) << 4;       // 0,16,32,48

    for (int i = 0; i < 16; i++) {
        const int s  = i & 1;
        const int n0 = i << 6;
        if (i >= 2) {
            if (s == 0) { MBAR_WAIT(sb + 8,  dph0); dph0 ^= 1; }
            else        { MBAR_WAIT(sb + 16, dph1); dph1 ^= 1; }
        }

        if (tx < 64) {
            ksm[tx] = ks[((size_t)(n0 + tx) * BATCH + b) * NHEAD + h];
            const bool mm = mask[(size_t)(n0 + tx) * BATCH + b] != 0;
            const unsigned bal = __ballot_sync(0xffffffffu, mm);
            if ((tx & 31) == 0) mbits[tx >> 5] = bal;
        }

        // V tile transpose
        {
            const __half* vp = v + ((size_t)(n0 + vn) * BATCH + b) * D_MODEL + h * DHEAD + dq;
            const uint4 va = *(const uint4*)vp;
            const uint4 vb_ = *(const uint4*)(vp + 8);
            const __half* h0 = (const __half*)&va;
            const __half* h1 = (const __half*)&vb_;
            char* vtb = sm + AT_V(s);
            const int nblk = vn >> 3;
            const int nrem = (vn & 7) << 1;
            #pragma unroll
            for (int e = 0; e < 8; e++) {
                const int d = dq + e;
                *(__half*)(vtb + d * 128 + ((nblk ^ (d & 7)) << 4) + nrem) = h0[e];
            }
            #pragma unroll
            for (int e = 0; e < 8; e++) {
                const int d = dq + 8 + e;
                *(__half*)(vtb + d * 128 + ((nblk ^ (d & 7)) << 4) + nrem) = h1[e];
            }
        }
        __syncthreads();

        // P compute: 32 exps per thread -> fp16 swizzled STS
        {
            const unsigned mb = mbits[nhalf];
            char* pb = sm + AT_P(s) + q * 128;
            #pragma unroll
            for (int g = 0; g < 4; g++) {
                __half ph[8];
                #pragma unroll
                for (int e = 0; e < 8; e++) {
                    const int np_ = g * 8 + e;
                    const float kv = ksm[nhalf * 32 + np_];
                    const float sc = ((mb >> np_) & 1u) ? -1000.0f : qv * kv;
                    ph[e] = __float2half_rn(__expf(sc - mq));
                    lpart += __half2float(ph[e]);
                }
                *(uint4*)(pb + (((nhalf * 4 + g) ^ q7) << 4)) = *(const uint4*)ph;
            }
        }
        FENCE_PROXY_ASYNC();
        __syncthreads();

        if (tx == 0) {
            TC_FENCE_AFTER();
            const uint64_t pd = MAKE_SMEM_DESC(sb + AT_P(s));
            const uint64_t vd = MAKE_SMEM_DESC(sb + AT_V(s));
            #pragma unroll
            for (int k8 = 0; k8 < 4; k8++)
                mma_f16_ss(tmem, pd + 2 * k8, vd + 2 * k8, AT_IDESC, (i | k8) ? 1u : 0u);
            TC_COMMIT(sb + 8 + s * 8);
        }
    }

    MBAR_WAIT(sb + 8,  dph0);
    MBAR_WAIT(sb + 16, dph1);
    lsum[tx] = lpart;
    __syncthreads();
    TC_FENCE_AFTER();

    const int w = tx >> 5;
    if (w < 4) {
        const int lane = tx & 31;
        const int ql   = w * 32 + lane;
        uint32_t d[64];
        TCGEN05_LD_32X32B_X32(d,      tmem);
        TCGEN05_LD_32X32B_X32(d + 32, tmem + 32);
        TCGEN05_WAIT_LD();

        const float inv = 1.f / (lsum[ql] + lsum[ql + 128]);
        const int row = (m0 + ql) * BATCH + b;
        const int rw7 = row & 7;
        #pragma unroll
        for (int jg = 0; jg < 16; jg++) {
            const int col = h * 64 + jg * 4;
            const __half2 h01 = __floats2half2_rn(__uint_as_float(d[jg * 4 + 0]) * inv,
                                                  __uint_as_float(d[jg * 4 + 1]) * inv);
            const __half2 h23 = __floats2half2_rn(__uint_as_float(d[jg * 4 + 2]) * inv,
                                                  __uint_as_float(d[jg * 4 + 3]) * inv);
            const size_t oidx = ((size_t)(col >> 6) * M_TOK + row) * 64 +
                                ((((col >> 3) & 7) ^ rw7) << 3) + (col & 7);
            __half2* dst = (__half2*)(pool + oidx);
            dst[0] = h01; dst[1] = h23;
        }
    }

    __syncthreads();
    if ((tx >> 5) == 0) TCGEN05_DEALLOC(tmem, 64);
#endif // HAS_TCGEN05
}

// ---------------- launcher (serial, single stream) ---------------------------
extern "C" void kernel_launch(void* const* d_in, const int* in_sizes, int n_in,
                              void* d_out, int out_size)
{
    const float* x     = (const float*)d_in[0];
    const unsigned char* mask = (const unsigned char*)d_in[1];
    const float* ln1_g = (const float*)d_in[2];
    const float* ln1_b = (const float*)d_in[3];
    const float* wq    = (const float*)d_in[4];
    const float* bq    = (const float*)d_in[5];
    const float* wk    = (const float*)d_in[6];
    const float* bk    = (const float*)d_in[7];
    const float* wv    = (const float*)d_in[8];
    const float* bv    = (const float*)d_in[9];
    const float* wo    = (const float*)d_in[10];
    const float* bo    = (const float*)d_in[11];
    const float* ln2_g = (const float*)d_in[12];
    const float* ln2_b = (const float*)d_in[13];
    const float* w1    = (const float*)d_in[14];
    const float* b1    = (const float*)d_in[15];
    const float* w2    = (const float*)d_in[16];
    const float* b2    = (const float*)d_in[17];
    float* out = (float*)d_out;

    float* scratch = nullptr;
    cudaGetSymbolAddress((void**)&scratch, g_scratch);
    __half* xn   = (__half*)(scratch + OFF_XN);
    __half* vbuf = (__half*)(scratch + OFF_V);
    __half* pool = (__half*)(scratch + OFF_POOL);
    float*  x2   = scratch + OFF_X2;
    __half* hbuf = (__half*)(scratch + OFF_H);
    float*  qsb  = scratch + OFF_QS;
    float*  ksb  = scratch + OFF_KS;
    float*  wqk  = scratch + OFF_WQK;
    float*  bqk  = scratch + OFF_BQK;
    __half* wvt  = (__half*)(scratch + OFF_WVT);
    __half* wot  = (__half*)(scratch + OFF_WOT);
    __half* w1t  = (__half*)(scratch + OFF_W1T);
    __half* w2t  = (__half*)(scratch + OFF_W2T);
    float4* kstat = (float4*)(scratch + OFF_KSTAT);

    cudaFuncSetAttribute(sgemm_tc<false, false, 2>, cudaFuncAttributeMaxDynamicSharedMemorySize, TC_SMEM_TOTAL);
    cudaFuncSetAttribute(sgemm_tc<false, true,  0>, cudaFuncAttributeMaxDynamicSharedMemorySize, TC_SMEM_TOTAL);
    cudaFuncSetAttribute(sgemm_tc<true,  false, 1>, cudaFuncAttributeMaxDynamicSharedMemorySize, TC_SMEM_TOTAL);
    cudaFuncSetAttribute(attn_kernel, cudaFuncAttributeMaxDynamicSharedMemorySize, AT_SMEM_TOTAL);

    // 0. weight prep: merged transposes + head sums
    transpose_all<<<10240, 256>>>(wv, wo, w1, w2, wvt, wot, w1t, w2t);
    headsum_kernel<<<64, 256>>>(wq, bq, wk, bk, wqk, bqk);
    // 1. xn = LN1(x)  (chunked fp16)
    ln_kernel<<<M_TOK, 256>>>(x, ln1_g, ln1_b, xn);
    // 2. v = xn @ wv + bv   (fp16 row-major out; 128 tiles, 1 iter)
    sgemm_tc<false, false, 2><<<TC_GRID, TC_THREADS, TC_SMEM_TOTAL>>>(
        xn, wvt, bv, nullptr, vbuf, D_MODEL, D_MODEL);
    // 3. qs/ks = xn @ wqk + bqk
    qsks_gemm<<<M_TOK / 32, 256>>>(xn, wqk, bqk, qsb, ksb);
    // 4. key stats for closed-form softmax max
    kminmax_kernel<<<BATCH * NHEAD, 256>>>(ksb, mask, kstat);
    // 5. pooled = softmax(qs ⊗ ks, masked) @ v   (chunked fp16 out)
    attn_kernel<<<dim3(SEQ / 128, BATCH * NHEAD), 256, AT_SMEM_TOTAL>>>(
        qsb, ksb, vbuf, mask, kstat, pool);
    // 6. x2 = pooled @ wo + bo + x   (fp32 row out)
    sgemm_tc<false, true, 0><<<TC_GRID, TC_THREADS, TC_SMEM_TOTAL>>>(
        pool, wot, bo, x, x2, D_MODEL, D_MODEL);
    // 7. xn = LN2(x2)
    ln_kernel<<<M_TOK, 256>>>(x2, ln2_g, ln2_b, xn);
    // 8. h = relu(xn @ w1 + b1)   (chunked fp16 out; 512 tiles, 4 iters/CTA)
    sgemm_tc<true, false, 1><<<TC_GRID, TC_THREADS, TC_SMEM_TOTAL>>>(
        xn, w1t, b1, nullptr, hbuf, FF_DIM, D_MODEL);
    // 9. out = h @ w2 + b2 + x2
    sgemm_tc<false, true, 0><<<TC_GRID, TC_THREADS, TC_SMEM_TOTAL>>>(
        hbuf, w2t, b2, x2, out, D_MODEL, FF_DIM);
}

// round 17
// speedup vs baseline: 1.0594x; 1.0122x over previous
#include <cuda_runtime.h>
#include <cuda_fp16.h>
#include <cstddef>
#include <cstdint>

// Problem constants
#define M_TOK   8192     // M*B token rows
#define D_MODEL 1024
#define FF_DIM  4096
#define NHEAD   16
#define DHEAD   64
#define SEQ     1024
#define BATCH   8

// tcgen05 is arch-SPECIFIC (sm_103a). nvcc also runs a generic compute_103 PTX
// pass where these instructions don't exist — compile a stub there.
#if defined(__CUDA_ARCH__) && (defined(__CUDA_ARCH_FEAT_SM103_ALL) || defined(__CUDA_ARCH_SPECIFIC__))
#define HAS_TCGEN05 1
#else
#define HAS_TCGEN05 0
#endif

// ---------------- tcgen05 / TMA helpers ----------------
static constexpr uint64_t SMEM_DESC_BASE_SW128 =
    (uint64_t(2)  << 61) | (uint64_t(1) << 46) | (uint64_t(64) << 32) | (uint64_t(1) << 16);
#define MAKE_SMEM_DESC(base_addr) \
    (SMEM_DESC_BASE_SW128 | ((uint64_t)((base_addr) >> 4) & 0x3FFF))

__device__ __forceinline__ uint32_t smem_to_u32(const void* p) {
    uint32_t a;
    asm("{ .reg .u64 t; cvta.to.shared.u64 t, %1; cvt.u32.u64 %0, t; }" : "=r"(a) : "l"(p));
    return a;
}

#if HAS_TCGEN05
#define TCGEN05_ALLOC(smem_res, nCols) \
    asm volatile("tcgen05.alloc.cta_group::1.sync.aligned.shared::cta.b32 [%0], %1;" \
                 :: "r"((uint32_t)(smem_res)), "r"((uint32_t)(nCols)) : "memory")
#define TCGEN05_DEALLOC(tmem, nCols) \
    asm volatile("tcgen05.dealloc.cta_group::1.sync.aligned.b32 %0, %1;" \
                 :: "r"(tmem), "r"((uint32_t)(nCols)))
#define TCGEN05_RELINQUISH() \
    asm volatile("tcgen05.relinquish_alloc_permit.cta_group::1.sync.aligned;")
#define TCGEN05_WAIT_LD() asm volatile("tcgen05.wait::ld.sync.aligned;" ::: "memory")
#define TC_FENCE_AFTER()  asm volatile("tcgen05.fence::after_thread_sync;" ::: "memory")
#define TC_COMMIT(mbar) \
    asm volatile("tcgen05.commit.cta_group::1.mbarrier::arrive::one.shared::cluster.b64 [%0];" \
                 :: "r"((uint32_t)(mbar)) : "memory")
#endif

#define FENCE_PROXY_ASYNC() asm volatile("fence.proxy.async.shared::cta;" ::: "memory")
#define MBARRIER_INIT(mbar, cnt) \
    asm volatile("mbarrier.init.shared.b64 [%0], %1;" :: "r"((uint32_t)(mbar)), "r"((uint32_t)(cnt)) : "memory")
#define MBARRIER_EXPECT_TX(mbar, bytes) \
    asm volatile("mbarrier.arrive.expect_tx.shared.b64 _, [%0], %1;" \
                 :: "r"((uint32_t)(mbar)), "r"((uint32_t)(bytes)) : "memory")
#define MBARRIER_ARRIVE(mbar) \
    asm volatile("mbarrier.arrive.shared.b64 _, [%0];" :: "r"((uint32_t)(mbar)) : "memory")
#define MBAR_WAIT(mbar, ph) \
    asm volatile("{\n\t.reg .pred P;\n\tWL%=:\n\t" \
                 "mbarrier.try_wait.parity.acquire.cta.shared::cta.b64 P, [%0], %1, 0x989680;\n\t" \
                 "@!P bra WL%=;\n\t}" :: "r"((uint32_t)(mbar)), "r"((uint32_t)(ph)) : "memory")
#define BULK_G2S(dst, src, bytes, mbar) \
    asm volatile("cp.async.bulk.shared::cta.global.mbarrier::complete_tx::bytes [%0], [%1], %2, [%3];" \
                 :: "r"((uint32_t)(dst)), "l"(src), "r"((uint32_t)(bytes)), "r"((uint32_t)(mbar)) : "memory")

#if HAS_TCGEN05
#define TCGEN05_LD_32X32B_X32(r, tmem_addr) \
    asm volatile( \
        "tcgen05.ld.sync.aligned.32x32b.x32.b32 " \
        "{%0, %1, %2, %3, %4, %5, %6, %7, " \
        " %8, %9, %10, %11, %12, %13, %14, %15, " \
        " %16, %17, %18, %19, %20, %21, %22, %23, " \
        " %24, %25, %26, %27, %28, %29, %30, %31}, [%32];" \
        : "=r"((r)[0]),  "=r"((r)[1]),  "=r"((r)[2]),  "=r"((r)[3]), \
          "=r"((r)[4]),  "=r"((r)[5]),  "=r"((r)[6]),  "=r"((r)[7]), \
          "=r"((r)[8]),  "=r"((r)[9]),  "=r"((r)[10]), "=r"((r)[11]), \
          "=r"((r)[12]), "=r"((r)[13]), "=r"((r)[14]), "=r"((r)[15]), \
          "=r"((r)[16]), "=r"((r)[17]), "=r"((r)[18]), "=r"((r)[19]), \
          "=r"((r)[20]), "=r"((r)[21]), "=r"((r)[22]), "=r"((r)[23]), \
          "=r"((r)[24]), "=r"((r)[25]), "=r"((r)[26]), "=r"((r)[27]), \
          "=r"((r)[28]), "=r"((r)[29]), "=r"((r)[30]), "=r"((r)[31]) \
        : "r"(tmem_addr))

// f16 SS MMA, cg1. idesc: dtype F32(1<<4) | atype F16(0) | btype F16(0)
//                        | (N/8)<<17 | (M/16)<<24
__device__ __forceinline__ void mma_f16_ss(uint32_t d_tmem, uint64_t a_desc, uint64_t b_desc,
                                           uint32_t idesc, uint32_t en)
{
    asm volatile(
        "{\n\t"
        ".reg .pred p;\n\t"
        "setp.ne.u32 p, %5, 0;\n\t"
        "tcgen05.mma.cta_group::1.kind::f16 [%0], %1, %2, %3, {%4, %4, %4, %4}, p;\n\t"
        "}"
        :: "r"(d_tmem), "l"(a_desc), "l"(b_desc), "r"(idesc), "r"(0u), "r"(en)
        : "memory");
}
#endif

// ============ chunked + pre-swizzled fp16 GEMM operand layout =================
__device__ __forceinline__ size_t hchunk_idx(int row, int k, int R) {
    return ((size_t)(k >> 6) * R + row) * 64 + ((((k >> 3) & 7) ^ (row & 7)) << 3) + (k & 7);
}

// ---------------- scratch (static device memory; float-array backing) --------
static const size_t OFF_XN    = 0;          // half [16][8192][64]
static const size_t OFF_V     = 4194304;    // half row-major [8192][1024]
static const size_t OFF_POOL  = 8388608;    // half chunked
static const size_t OFF_X2    = 12582912;   // fp32 [8192][1024]
static const size_t OFF_H     = 20971520;   // half chunked [64][8192][64]
static const size_t OFF_QS    = 37748736;
static const size_t OFF_KS    = 37879808;
static const size_t OFF_WQK   = 38010880;   // fp32 [1024][32]
static const size_t OFF_BQK   = 38043648;
static const size_t OFF_WVT   = 38043680;   // half chunked
static const size_t OFF_WOT   = 38567968;
static const size_t OFF_W1T   = 39092256;
static const size_t OFF_W2T   = 41189408;
static const size_t OFF_KSTAT = 43286560;
static const size_t OFF_VT    = 43287072;   // half [128 bh][16 tile][64 d][64 n sw]
static const size_t SCRATCH_FLOATS = 47481376;

__device__ float g_scratch[SCRATCH_FLOATS];

// ---------------- LayerNorm: row-major fp32 in -> chunked fp16 out ----------
__global__ void __launch_bounds__(256)
ln_kernel(const float* __restrict__ x, const float* __restrict__ g,
          const float* __restrict__ bta, __half* __restrict__ y)
{
    const int row = blockIdx.x;
    const int tx  = threadIdx.x;
    const float4 v = ((const float4*)(x + (size_t)row * D_MODEL))[tx];

    float s  = v.x + v.y + v.z + v.w;
    float sq = v.x * v.x + v.y * v.y + v.z * v.z + v.w * v.w;
    #pragma unroll
    for (int o = 16; o; o >>= 1) {
        s  += __shfl_xor_sync(0xffffffffu, s,  o);
        sq += __shfl_xor_sync(0xffffffffu, sq, o);
    }
    __shared__ float ss[8], ssq[8];
    const int w = tx >> 5, l = tx & 31;
    if (l == 0) { ss[w] = s; ssq[w] = sq; }
    __syncthreads();
    s = 0.f; sq = 0.f;
    #pragma unroll
    for (int i = 0; i < 8; i++) { s += ss[i]; sq += ssq[i]; }

    const float mean = s * (1.f / D_MODEL);
    const float var  = sq * (1.f / D_MODEL) - mean * mean;
    const float rstd = rsqrtf(var + 1e-5f);

    const float4 gv = ((const float4*)g)[tx];
    const float4 bv = ((const float4*)bta)[tx];
    const __half2 h01 = __floats2half2_rn((v.x - mean) * rstd * gv.x + bv.x,
                                          (v.y - mean) * rstd * gv.y + bv.y);
    const __half2 h23 = __floats2half2_rn((v.z - mean) * rstd * gv.z + bv.z,
                                          (v.w - mean) * rstd * gv.w + bv.w);
    const size_t oidx = ((size_t)(tx >> 4) * M_TOK + row) * 64 +
                        ((((tx >> 1) & 7) ^ (row & 7)) << 3) + ((tx & 1) << 2);
    __half2* dst = (__half2*)(y + oidx);
    dst[0] = h01; dst[1] = h23;
}

// ---------------- merged transpose: all 4 weights -> chunked fp16 -----------
__global__ void __launch_bounds__(256)
transpose_all(const float* __restrict__ wv, const float* __restrict__ wo,
              const float* __restrict__ w1, const float* __restrict__ w2,
              __half* __restrict__ wvt, __half* __restrict__ wot,
              __half* __restrict__ w1t, __half* __restrict__ w2t)
{
    int bid = blockIdx.x;
    const float* in; __half* out; int N;
    if (bid < 1024)      { in = wv; out = wvt; N = 1024; }
    else if (bid < 2048) { bid -= 1024; in = wo; out = wot; N = 1024; }
    else if (bid < 6144) { bid -= 2048; in = w1; out = w1t; N = 4096; }
    else                 { bid -= 6144; in = w2; out = w2t; N = 1024; }
    const int nbx = N >> 5;
    const int n0 = (bid % nbx) << 5;
    const int k0 = (bid / nbx) << 5;

    __shared__ float t[32][33];
    const int tx = threadIdx.x & 31;
    const int ty = threadIdx.x >> 5;   // 0..7
    #pragma unroll
    for (int i = 0; i < 4; i++)
        t[ty + (i << 3)][tx] = in[(size_t)(k0 + ty + (i << 3)) * N + n0 + tx];
    __syncthreads();
    #pragma unroll
    for (int i = 0; i < 4; i++) {
        const int n = n0 + ty + (i << 3);
        const int k = k0 + tx;
        out[hchunk_idx(n, k, N)] = __float2half_rn(t[tx][ty + (i << 3)]);
    }
}

// ---------------- head-sum of wq/wk columns into combined [1024][32] ---------
__global__ void headsum_kernel(const float* __restrict__ wq, const float* __restrict__ bq,
                               const float* __restrict__ wk, const float* __restrict__ bk,
                               float* __restrict__ wqk, float* __restrict__ bqk)
{
    const int idx = blockIdx.x * blockDim.x + threadIdx.x;
    if (idx < D_MODEL * NHEAD) {
        const int d = idx >> 4, h = idx & 15;
        const float* pq = wq + (size_t)d * D_MODEL + h * DHEAD;
        const float* pk = wk + (size_t)d * D_MODEL + h * DHEAD;
        float sq = 0.f, sk = 0.f;
        #pragma unroll 8
        for (int i = 0; i < DHEAD; i++) { sq += pq[i]; sk += pk[i]; }
        wqk[d * 32 + h]      = sq;
        wqk[d * 32 + 16 + h] = sk;
    }
    if (idx < NHEAD) {
        float sq = 0.f, sk = 0.f;
        for (int i = 0; i < DHEAD; i++) {
            sq += bq[idx * DHEAD + i];
            sk += bk[idx * DHEAD + i];
        }
        bqk[idx] = sq; bqk[16 + idx] = sk;
    }
}

// ---------------- skinny GEMM v3: 256 blocks x 32 rows -----------------------
__global__ void __launch_bounds__(256)
qsks_gemm(const __half* __restrict__ xn, const float* __restrict__ wqk,
          const float* __restrict__ bqk, float* __restrict__ qs, float* __restrict__ ks)
{
    __shared__ __half Araw[2048];     // 32 rows x 64 halves = 256 uint4
    __shared__ float Wsm[64][36];

    const int tx = threadIdx.x;
    const int r  = tx >> 3;           // 0..31
    const int cg = tx & 7;
    const int brow = blockIdx.x << 5;
    const int p7 = r & 7;

    float acc[4];
    #pragma unroll
    for (int j = 0; j < 4; j++) acc[j] = 0.f;

    for (int chk = 0; chk < 16; chk++) {
        {
            const uint4* src = (const uint4*)(xn + ((size_t)chk * M_TOK + brow) * 64);
            ((uint4*)Araw)[tx] = src[tx];
        }
        {
            const int row = tx >> 3, c4 = (tx & 7) << 2;
            *(float4*)&Wsm[row][c4]      = *(const float4*)(wqk + (size_t)(chk * 64 + row) * 32 + c4);
            *(float4*)&Wsm[row + 32][c4] = *(const float4*)(wqk + (size_t)(chk * 64 + row + 32) * 32 + c4);
        }
        __syncthreads();

        #pragma unroll
        for (int j = 0; j < 8; j++) {
            const uint4 ab = *(const uint4*)&Araw[r * 64 + ((j ^ p7) << 3)];
            const __half2* hp = (const __half2*)&ab;
            #pragma unroll
            for (int e = 0; e < 4; e++) {
                const float2 f2 = __half22float2(hp[e]);
                const int kk = j * 8 + e * 2;
                {
                    const float4 w0 = *(const float4*)&Wsm[kk][cg * 4];
                    acc[0] = fmaf(f2.x, w0.x, acc[0]); acc[1] = fmaf(f2.x, w0.y, acc[1]);
                    acc[2] = fmaf(f2.x, w0.z, acc[2]); acc[3] = fmaf(f2.x, w0.w, acc[3]);
                }
                {
                    const float4 w0 = *(const float4*)&Wsm[kk + 1][cg * 4];
                    acc[0] = fmaf(f2.y, w0.x, acc[0]); acc[1] = fmaf(f2.y, w0.y, acc[1]);
                    acc[2] = fmaf(f2.y, w0.z, acc[2]); acc[3] = fmaf(f2.y, w0.w, acc[3]);
                }
            }
        }
        __syncthreads();
    }

    const size_t row = (size_t)(brow + r);
    #pragma unroll
    for (int j = 0; j < 4; j++) {
        const int c = cg * 4 + j;
        const float v = acc[j] + bqk[c];
        if (c < 16) qs[row * NHEAD + c]        = v;
        else        ks[row * NHEAD + (c - 16)] = v;
    }
}

// ---------------- per-(b,h) key stats ----------------------------------------
__global__ void __launch_bounds__(256)
kminmax_kernel(const float* __restrict__ ks, const unsigned char* __restrict__ mask,
               float4* __restrict__ kstat)
{
    const int bh = blockIdx.x;
    const int b  = bh >> 4;
    const int h  = bh & 15;
    const int tx = threadIdx.x;

    float kmx = -1e30f, kmn = 1e30f;
    int cnt = 0, anym = 0;
    for (int n = tx; n < SEQ; n += 256) {
        const float kv = ks[((size_t)n * BATCH + b) * NHEAD + h];
        if (mask[(size_t)n * BATCH + b]) anym = 1;
        else { kmx = fmaxf(kmx, kv); kmn = fminf(kmn, kv); cnt++; }
    }
    __shared__ float smx[256], smn[256];
    __shared__ int scnt[256], sany[256];
    smx[tx] = kmx; smn[tx] = kmn; scnt[tx] = cnt; sany[tx] = anym;
    __syncthreads();
    for (int o = 128; o; o >>= 1) {
        if (tx < o) {
            smx[tx] = fmaxf(smx[tx], smx[tx + o]);
            smn[tx] = fminf(smn[tx], smn[tx + o]);
            scnt[tx] += scnt[tx + o];
            sany[tx] |= sany[tx + o];
        }
        __syncthreads();
    }
    if (tx == 0)
        kstat[bh] = make_float4(smx[0], smn[0], sany[0] ? 1.f : 0.f, (float)scnt[0]);
}

// ---------------- V-transpose: row-major vbuf -> per-(bh,tile) 8KB B-operand --
// vt[((bh*16+tile)*64 + d)*64 + (((n>>3)^(d&7))<<3) + (n&7)] = V[token(n,b)][h*64+d]
__global__ void __launch_bounds__(256)
vt_kernel(const __half* __restrict__ v, __half* __restrict__ vt)
{
    const int bh   = blockIdx.x >> 4;
    const int tile = blockIdx.x & 15;
    const int b = bh >> 4, h = bh & 15;
    const int tx = threadIdx.x;
    __half* base = vt + ((size_t)blockIdx.x * 64) * 64;

    #pragma unroll
    for (int it = 0; it < 2; it++) {
        const int idx  = tx + (it << 8);   // 0..511
        const int d    = idx >> 3;         // 0..63
        const int nblk = idx & 7;          // 0..7
        __half h8[8];
        #pragma unroll
        for (int e = 0; e < 8; e++) {
            const int n = nblk * 8 + e;
            const int token = (tile * 64 + n) * BATCH + b;
            h8[e] = v[(size_t)token * D_MODEL + h * DHEAD + d];
        }
        *(uint4*)(base + d * 64 + ((nblk ^ (d & 7)) << 3)) = *(const uint4*)h8;
    }
}

// ======== persistent tcgen05 f16 GEMM: 256x256 tiles, warp-specialized =========
#define TC_STAGES   3
#define TC_HDR      1024
#define TC_STAGE_SZ 65536
#define TC_SMEM_TOTAL (TC_HDR + TC_STAGES * TC_STAGE_SZ)   // 197632
#define TC_IDESC  ((1u << 4) | (32u << 17) | (8u << 24))   // f16, N=256, M=128
#define TC_GRID   128
#define TC_THREADS 320
// mbarrier layout: full[s]@8+8s  done[s]@32+8s  epi_full@56  epi_done@64

template<bool RELU, bool RESID, int OUTMODE>
__global__ void __launch_bounds__(TC_THREADS)
sgemm_tc(const __half* __restrict__ A, const __half* __restrict__ Wt,
         const float* __restrict__ bias, const float* __restrict__ resid,
         void* __restrict__ C, int N, int K)
{
#if HAS_TCGEN05
    extern __shared__ char sm[];
    const uint32_t sb = smem_to_u32(sm);
    const int tx = threadIdx.x;
    const int nN     = N >> 8;
    const int niter  = ((M_TOK >> 8) * nN) >> 7;
    const int nchunk = K >> 6;

    if ((tx >> 5) == 0) TCGEN05_ALLOC(sb, 512);
    if (tx == 0) {
        #pragma unroll
        for (int s = 0; s < TC_STAGES; s++) {
            MBARRIER_INIT(sb + 8 + s * 8, 1);
            MBARRIER_INIT(sb + 32 + s * 8, 1);
        }
        MBARRIER_INIT(sb + 56, 1);
        MBARRIER_INIT(sb + 64, 8);
    }
    __syncthreads();
    if ((tx >> 5) == 0) TCGEN05_RELINQUISH();
    uint32_t tmem;
    asm volatile("ld.shared.b32 %0, [%1];" : "=r"(tmem) : "r"(sb));

    if (tx == 256) {
        TC_FENCE_AFTER();
        int phF0 = 0, phF1 = 0, phF2 = 0;
        int g = 0;
        for (int it = 0; it < niter; it++) {
            if (it > 0) MBAR_WAIT(sb + 64, (it - 1) & 1);
            for (int c = 0; c < nchunk; c++, g++) {
                const int s = g % TC_STAGES;
                int ph;
                if (s == 0)      { ph = phF0; phF0 ^= 1; }
                else if (s == 1) { ph = phF1; phF1 ^= 1; }
                else             { ph = phF2; phF2 ^= 1; }
                MBAR_WAIT(sb + 8 + s * 8, ph);
                const uint32_t abase = sb + TC_HDR + s * TC_STAGE_SZ;
                const uint64_t ad0 = MAKE_SMEM_DESC(abase);
                const uint64_t ad1 = MAKE_SMEM_DESC(abase + 16384);
                const uint64_t bd  = MAKE_SMEM_DESC(abase + 32768);
                #pragma unroll
                for (int k8 = 0; k8 < 4; k8++) {
                    const uint32_t en = (c | k8) ? 1u : 0u;
                    mma_f16_ss(tmem,       ad0 + 2 * k8, bd + 2 * k8, TC_IDESC, en);
                    mma_f16_ss(tmem + 256, ad1 + 2 * k8, bd + 2 * k8, TC_IDESC, en);
                }
                TC_COMMIT(sb + 32 + s * 8);
            }
            TC_COMMIT(sb + 56);
        }
    } else if (tx == 288) {
        int phD0 = 0, phD1 = 0, phD2 = 0;
        int g = 0;
        for (int it = 0; it < niter; it++) {
            const int t = blockIdx.x + (it << 7);
            const int brow = (t / nN) << 8;
            const int bcol = (t % nN) << 8;
            for (int c = 0; c < nchunk; c++, g++) {
                const int s = g % TC_STAGES;
                if (g >= TC_STAGES) {
                    int ph;
                    if (s == 0)      { ph = phD0; phD0 ^= 1; }
                    else if (s == 1) { ph = phD1; phD1 ^= 1; }
                    else             { ph = phD2; phD2 ^= 1; }
                    MBAR_WAIT(sb + 32 + s * 8, ph);
                }
                const uint32_t abase = sb + TC_HDR + s * TC_STAGE_SZ;
                const uint32_t full = sb + 8 + s * 8;
                MBARRIER_EXPECT_TX(full, 2 * 32768);
                BULK_G2S(abase,         A + ((size_t)c * M_TOK + brow) * 64, 32768, full);
                BULK_G2S(abase + 32768, Wt + ((size_t)c * N + bcol) * 64, 32768, full);
            }
        }
    } else if (tx < 256) {
        const int w     = tx >> 5;
        const int lane  = tx & 31;
        const int mtile = w >> 2;
        for (int it = 0; it < niter; it++) {
            const int t = blockIdx.x + (it << 7);
            const int brow = (t / nN) << 8;
            const int bcol = (t % nN) << 8;
            MBAR_WAIT(sb + 56, it & 1);
            TC_FENCE_AFTER();
            const int row = brow + (mtile << 7) + ((w & 3) << 5) + lane;
            const int rw7 = row & 7;
            #pragma unroll
            for (int slab = 0; slab < 4; slab++) {
                uint32_t d[64];
                TCGEN05_LD_32X32B_X32(d,      tmem + mtile * 256 + slab * 64);
                TCGEN05_LD_32X32B_X32(d + 32, tmem + mtile * 256 + slab * 64 + 32);
                TCGEN05_WAIT_LD();
                if (slab == 3 && lane == 0) MBARRIER_ARRIVE(sb + 64);
                const int cb = bcol + slab * 64;
                const float* bp = bias + cb;
                const float* rp = RESID ? (resid + (size_t)row * N + cb) : nullptr;
                #pragma unroll
                for (int j = 0; j < 64; j += 4) {
                    const float4 bv = *(const float4*)(bp + j);
                    float4 o;
                    o.x = __uint_as_float(d[j + 0]) + bv.x;
                    o.y = __uint_as_float(d[j + 1]) + bv.y;
                    o.z = __uint_as_float(d[j + 2]) + bv.z;
                    o.w = __uint_as_float(d[j + 3]) + bv.w;
                    if (RESID) {
                        const float4 rv = *(const float4*)(rp + j);
                        o.x += rv.x; o.y += rv.y; o.z += rv.z; o.w += rv.w;
                    }
                    if (RELU) {
                        o.x = fmaxf(o.x, 0.f); o.y = fmaxf(o.y, 0.f);
                        o.z = fmaxf(o.z, 0.f); o.w = fmaxf(o.w, 0.f);
                    }
                    if (OUTMODE == 1) {
                        const int col = cb + j;
                        const __half2 h01 = __floats2half2_rn(o.x, o.y);
                        const __half2 h23 = __floats2half2_rn(o.z, o.w);
                        const size_t oidx = ((size_t)(col >> 6) * M_TOK + row) * 64 +
                                            ((((col >> 3) & 7) ^ rw7) << 3) + (col & 7);
                        __half2* dst = (__half2*)((__half*)C + oidx);
                        dst[0] = h01; dst[1] = h23;
                    } else if (OUTMODE == 2) {
                        const __half2 h01 = __floats2half2_rn(o.x, o.y);
                        const __half2 h23 = __floats2half2_rn(o.z, o.w);
                        __half2* dst = (__half2*)((__half*)C + (size_t)row * N + cb + j);
                        dst[0] = h01; dst[1] = h23;
                    } else {
                        *(float4*)((float*)C + (size_t)row * N + cb + j) = o;
                    }
                }
            }
        }
    }
    __syncthreads();
    if ((tx >> 5) == 0) TCGEN05_DEALLOC(tmem, 512);
#endif // HAS_TCGEN05
}

// ================= tensor-core attention (fp16, TMA-loaded Vt) ===============
// smem: 0 tmemptr | 8,16 done mbars | 24,32 vfull mbars | 64 lsum | 1088 ksm |
//       1344 mbits | 2048 P0 | 18432 P1 | 34816 V0(8KB) | 43008 V1
#define AT_SMEM_TOTAL 51200
#define AT_P(s)   (2048 + (s) * 16384)
#define AT_V(s)   (34816 + (s) * 8192)
#define AT_IDESC  ((1u << 4) | (8u << 17) | (8u << 24))   // f16, N=64, M=128

__global__ void __launch_bounds__(256)
attn_kernel(const float* __restrict__ qs, const float* __restrict__ ks,
            const __half* __restrict__ vt, const unsigned char* __restrict__ mask,
            const float4* __restrict__ kstat, __half* __restrict__ pool)
{
#if HAS_TCGEN05
    extern __shared__ char sm[];
    const uint32_t sb = smem_to_u32(sm);
    float* lsum = (float*)(sm + 64);
    float* ksm  = (float*)(sm + 1088);
    unsigned* mbits = (unsigned*)(sm + 1344);

    const int tx = threadIdx.x;
    const int bh = blockIdx.y;
    const int b  = bh >> 4;
    const int h  = bh & 15;
    const int m0 = blockIdx.x << 7;

    const int q     = tx & 127;
    const int nhalf = tx >> 7;
    const int q7    = q & 7;

    if ((tx >> 5) == 0) TCGEN05_ALLOC(sb, 64);
    if (tx == 0) {
        MBARRIER_INIT(sb + 8, 1);  MBARRIER_INIT(sb + 16, 1);   // done[s]
        MBARRIER_INIT(sb + 24, 1); MBARRIER_INIT(sb + 32, 1);   // vfull[s]
    }
    __syncthreads();
    if ((tx >> 5) == 0) TCGEN05_RELINQUISH();
    uint32_t tmem;
    asm volatile("ld.shared.b32 %0, [%1];" : "=r"(tmem) : "r"(sb));

    const float qv = qs[((size_t)(m0 + q) * BATCH + b) * NHEAD + h];
    const float4 kst = kstat[bh];
    float mu = (kst.w > 0.f) ? fmaxf(qv * kst.x, qv * kst.y) : -1e30f;
    const float mq = (kst.z > 0.f) ? fmaxf(mu, -1000.0f) : mu;

    float lpart = 0.f;
    int dph0 = 0, dph1 = 0;

    const __half* vtb_g = vt + ((size_t)bh * 16) * 4096;

    for (int i = 0; i < 16; i++) {
        const int s  = i & 1;
        const int n0 = i << 6;
        if (i >= 2) {
            if (s == 0) { MBAR_WAIT(sb + 8,  dph0); dph0 ^= 1; }
            else        { MBAR_WAIT(sb + 16, dph1); dph1 ^= 1; }
        }

        // async Vt tile fill (overlaps P compute below)
        if (tx == 0) {
            const uint32_t vfull = sb + 24 + s * 8;
            MBARRIER_EXPECT_TX(vfull, 8192);
            BULK_G2S(sb + AT_V(s), vtb_g + (size_t)i * 4096, 8192, vfull);
        }

        if (tx < 64) {
            ksm[tx] = ks[((size_t)(n0 + tx) * BATCH + b) * NHEAD + h];
            const bool mm = mask[(size_t)(n0 + tx) * BATCH + b] != 0;
            const unsigned bal = __ballot_sync(0xffffffffu, mm);
            if ((tx & 31) == 0) mbits[tx >> 5] = bal;
        }
        __syncthreads();

        // P compute: 32 exps per thread -> fp16 swizzled STS
        {
            const unsigned mb = mbits[nhalf];
            char* pb = sm + AT_P(s) + q * 128;
            #pragma unroll
            for (int g = 0; g < 4; g++) {
                __half ph[8];
                #pragma unroll
                for (int e = 0; e < 8; e++) {
                    const int np_ = g * 8 + e;
                    const float kv = ksm[nhalf * 32 + np_];
                    const float sc = ((mb >> np_) & 1u) ? -1000.0f : qv * kv;
                    ph[e] = __float2half_rn(__expf(sc - mq));
                    lpart += __half2float(ph[e]);
                }
                *(uint4*)(pb + (((nhalf * 4 + g) ^ q7) << 4)) = *(const uint4*)ph;
            }
        }
        FENCE_PROXY_ASYNC();
        __syncthreads();

        if (tx == 0) {
            MBAR_WAIT(sb + 24 + s * 8, (i >> 1) & 1);   // Vt tile landed
            TC_FENCE_AFTER();
            const uint64_t pd = MAKE_SMEM_DESC(sb + AT_P(s));
            const uint64_t vd = MAKE_SMEM_DESC(sb + AT_V(s));
            #pragma unroll
            for (int k8 = 0; k8 < 4; k8++)
                mma_f16_ss(tmem, pd + 2 * k8, vd + 2 * k8, AT_IDESC, (i | k8) ? 1u : 0u);
            TC_COMMIT(sb + 8 + s * 8);
        }
    }

    MBAR_WAIT(sb + 8,  dph0);
    MBAR_WAIT(sb + 16, dph1);
    lsum[tx] = lpart;
    __syncthreads();
    TC_FENCE_AFTER();

    const int w = tx >> 5;
    if (w < 4) {
        const int lane = tx & 31;
        const int ql   = w * 32 + lane;
        uint32_t d[64];
        TCGEN05_LD_32X32B_X32(d,      tmem);
        TCGEN05_LD_32X32B_X32(d + 32, tmem + 32);
        TCGEN05_WAIT_LD();

        const float inv = 1.f / (lsum[ql] + lsum[ql + 128]);
        const int row = (m0 + ql) * BATCH + b;
        const int rw7 = row & 7;
        #pragma unroll
        for (int jg = 0; jg < 16; jg++) {
            const int col = h * 64 + jg * 4;
            const __half2 h01 = __floats2half2_rn(__uint_as_float(d[jg * 4 + 0]) * inv,
                                                  __uint_as_float(d[jg * 4 + 1]) * inv);
            const __half2 h23 = __floats2half2_rn(__uint_as_float(d[jg * 4 + 2]) * inv,
                                                  __uint_as_float(d[jg * 4 + 3]) * inv);
            const size_t oidx = ((size_t)(col >> 6) * M_TOK + row) * 64 +
                                ((((col >> 3) & 7) ^ rw7) << 3) + (col & 7);
            __half2* dst = (__half2*)(pool + oidx);
            dst[0] = h01; dst[1] = h23;
        }
    }

    __syncthreads();
    if ((tx >> 5) == 0) TCGEN05_DEALLOC(tmem, 64);
#endif // HAS_TCGEN05
}

// ---------------- launcher (serial, single stream) ---------------------------
extern "C" void kernel_launch(void* const* d_in, const int* in_sizes, int n_in,
                              void* d_out, int out_size)
{
    const float* x     = (const float*)d_in[0];
    const unsigned char* mask = (const unsigned char*)d_in[1];
    const float* ln1_g = (const float*)d_in[2];
    const float* ln1_b = (const float*)d_in[3];
    const float* wq    = (const float*)d_in[4];
    const float* bq    = (const float*)d_in[5];
    const float* wk    = (const float*)d_in[6];
    const float* bk    = (const float*)d_in[7];
    const float* wv    = (const float*)d_in[8];
    const float* bv    = (const float*)d_in[9];
    const float* wo    = (const float*)d_in[10];
    const float* bo    = (const float*)d_in[11];
    const float* ln2_g = (const float*)d_in[12];
    const float* ln2_b = (const float*)d_in[13];
    const float* w1    = (const float*)d_in[14];
    const float* b1    = (const float*)d_in[15];
    const float* w2    = (const float*)d_in[16];
    const float* b2    = (const float*)d_in[17];
    float* out = (float*)d_out;

    float* scratch = nullptr;
    cudaGetSymbolAddress((void**)&scratch, g_scratch);
    __half* xn   = (__half*)(scratch + OFF_XN);
    __half* vbuf = (__half*)(scratch + OFF_V);
    __half* pool = (__half*)(scratch + OFF_POOL);
    float*  x2   = scratch + OFF_X2;
    __half* hbuf = (__half*)(scratch + OFF_H);
    float*  qsb  = scratch + OFF_QS;
    float*  ksb  = scratch + OFF_KS;
    float*  wqk  = scratch + OFF_WQK;
    float*  bqk  = scratch + OFF_BQK;
    __half* wvt  = (__half*)(scratch + OFF_WVT);
    __half* wot  = (__half*)(scratch + OFF_WOT);
    __half* w1t  = (__half*)(scratch + OFF_W1T);
    __half* w2t  = (__half*)(scratch + OFF_W2T);
    float4* kstat = (float4*)(scratch + OFF_KSTAT);
    __half* vtb  = (__half*)(scratch + OFF_VT);

    cudaFuncSetAttribute(sgemm_tc<false, false, 2>, cudaFuncAttributeMaxDynamicSharedMemorySize, TC_SMEM_TOTAL);
    cudaFuncSetAttribute(sgemm_tc<false, true,  0>, cudaFuncAttributeMaxDynamicSharedMemorySize, TC_SMEM_TOTAL);
    cudaFuncSetAttribute(sgemm_tc<true,  false, 1>, cudaFuncAttributeMaxDynamicSharedMemorySize, TC_SMEM_TOTAL);
    cudaFuncSetAttribute(attn_kernel, cudaFuncAttributeMaxDynamicSharedMemorySize, AT_SMEM_TOTAL);

    // 0. weight prep: merged transposes + head sums
    transpose_all<<<10240, 256>>>(wv, wo, w1, w2, wvt, wot, w1t, w2t);
    headsum_kernel<<<64, 256>>>(wq, bq, wk, bk, wqk, bqk);
    // 1. xn = LN1(x)  (chunked fp16)
    ln_kernel<<<M_TOK, 256>>>(x, ln1_g, ln1_b, xn);
    // 2. v = xn @ wv + bv   (fp16 row-major out)
    sgemm_tc<false, false, 2><<<TC_GRID, TC_THREADS, TC_SMEM_TOTAL>>>(
        xn, wvt, bv, nullptr, vbuf, D_MODEL, D_MODEL);
    // 3. qs/ks = xn @ wqk + bqk
    qsks_gemm<<<M_TOK / 32, 256>>>(xn, wqk, bqk, qsb, ksb);
    // 4. key stats + per-(bh,tile) Vt B-operand blocks
    kminmax_kernel<<<BATCH * NHEAD, 256>>>(ksb, mask, kstat);
    vt_kernel<<<BATCH * NHEAD * 16, 256>>>(vbuf, vtb);
    // 5. pooled = softmax(qs ⊗ ks, masked) @ v   (chunked fp16 out)
    attn_kernel<<<dim3(SEQ / 128, BATCH * NHEAD), 256, AT_SMEM_TOTAL>>>(
        qsb, ksb, vtb, mask, kstat, pool);
    // 6. x2 = pooled @ wo + bo + x   (fp32 row out)
    sgemm_tc<false, true, 0><<<TC_GRID, TC_THREADS, TC_SMEM_TOTAL>>>(
        pool, wot, bo, x, x2, D_MODEL, D_MODEL);
    // 7. xn = LN2(x2)
    ln_kernel<<<M_TOK, 256>>>(x2, ln2_g, ln2_b, xn);
    // 8. h = relu(xn @ w1 + b1)   (chunked fp16 out)
    sgemm_tc<true, false, 1><<<TC_GRID, TC_THREADS, TC_SMEM_TOTAL>>>(
        xn, w1t, b1, nullptr, hbuf, FF_DIM, D_MODEL);
    // 9. out = h @ w2 + b2 + x2
    sgemm_tc<false, true, 0><<<TC_GRID, TC_THREADS, TC_SMEM_TOTAL>>>(
        hbuf, w2t, b2, x2, out, D_MODEL, FF_DIM);
}